// round 8
// baseline (speedup 1.0000x reference)
#include <cuda_runtime.h>
#include <cuda_fp16.h>
#include <cstdint>

#define PSHIFT 8.0f
#define PSCALE 0.000335462627902512f   // exp(-8)
#define E8F    2980.9580f              // exp(+8)

// scratch (N<=8192, S<=4096)
static __device__ float  g_partial[16384 * 64];   // per-row partial sumexp (64 chunks/row)
static __device__ __half g_P[16384 * 4096];       // P' = exp(cos+8), speech rows [0,N), face [N,2N)
static __device__ __half g_sp_h[8192 * 256];      // normalized speech
static __device__ __half g_fa_h[8192 * 256];      // normalized face
static __device__ __half g_svmn_h[4096 * 256];    // normalized svm (logits B)
static __device__ __half g_fkmn_h[4096 * 256];    // normalized fkm (logits B)
static __device__ __half g_svm_h[4096 * 256];     // RAW svm (recall V)

__device__ __forceinline__ unsigned pkh(float a, float b){
    __half2 h = __floats2half2_rn(a, b);
    return *reinterpret_cast<unsigned*>(&h);
}
__device__ __forceinline__ void cpa16(uint32_t dst, const void* src){
    asm volatile("cp.async.cg.shared.global [%0], [%1], 16;\n" :: "r"(dst), "l"(src));
}
#define CP_COMMIT asm volatile("cp.async.commit_group;\n" ::: "memory")
#define CP_WAIT(n) asm volatile("cp.async.wait_group %0;\n" :: "n"(n) : "memory")

__device__ __forceinline__ void ldsm4(unsigned r[4], const void* p){
    uint32_t a = (uint32_t)__cvta_generic_to_shared(p);
    asm volatile("ldmatrix.sync.aligned.m8n8.x4.shared.b16 {%0,%1,%2,%3}, [%4];\n"
        : "=r"(r[0]), "=r"(r[1]), "=r"(r[2]), "=r"(r[3]) : "r"(a));
}
__device__ __forceinline__ void ldsm4t(unsigned r[4], const void* p){
    uint32_t a = (uint32_t)__cvta_generic_to_shared(p);
    asm volatile("ldmatrix.sync.aligned.m8n8.x4.trans.shared.b16 {%0,%1,%2,%3}, [%4];\n"
        : "=r"(r[0]), "=r"(r[1]), "=r"(r[2]), "=r"(r[3]) : "r"(a));
}
__device__ __forceinline__ void mma16816(float c[4], const unsigned a[4], unsigned b0, unsigned b1){
    asm volatile("mma.sync.aligned.m16n8k16.row.col.f32.f16.f16.f32 "
        "{%0,%1,%2,%3}, {%4,%5,%6,%7}, {%8,%9}, {%0,%1,%2,%3};\n"
        : "+f"(c[0]), "+f"(c[1]), "+f"(c[2]), "+f"(c[3])
        : "r"(a[0]), "r"(a[1]), "r"(a[2]), "r"(a[3]), "r"(b0), "r"(b1));
}

// ------- fused convert(f32->f16) + row-normalize: one warp per row ---------
__global__ void convert_norms_kernel(const float* __restrict__ face, const float* __restrict__ speech,
                                     const float* __restrict__ svm, const float* __restrict__ fkm,
                                     int N, int S){
    int warp = threadIdx.x >> 5, lane = threadIdx.x & 31;
    int rid = blockIdx.x * 8 + warp;
    int total = 2*N + 2*S;
    if (rid >= total) return;
    const float* src; __half* hdst; __half* hraw = nullptr;
    if (rid < N)            { src = speech + (long)rid * 256; hdst = g_sp_h + (long)rid * 256; }
    else if (rid < 2*N)     { int r = rid - N; src = face + (long)r * 256; hdst = g_fa_h + (long)r * 256; }
    else if (rid < 2*N + S) { int r = rid - 2*N; src = svm + (long)r * 256;
                              hdst = g_svmn_h + (long)r * 256; hraw = g_svm_h + (long)r * 256; }
    else                    { int r = rid - 2*N - S; src = fkm + (long)r * 256; hdst = g_fkmn_h + (long)r * 256; }
    const float4* p = reinterpret_cast<const float4*>(src);
    float4 v0 = p[lane], v1 = p[lane + 32];
    float s = v0.x*v0.x + v0.y*v0.y + v0.z*v0.z + v0.w*v0.w
            + v1.x*v1.x + v1.y*v1.y + v1.z*v1.z + v1.w*v1.w;
    #pragma unroll
    for (int o = 16; o; o >>= 1) s += __shfl_xor_sync(0xffffffffu, s, o);
    float inv = rsqrtf(s);
    uint2* up = reinterpret_cast<uint2*>(hdst);
    up[lane]      = make_uint2(pkh(v0.x*inv, v0.y*inv), pkh(v0.z*inv, v0.w*inv));
    up[lane + 32] = make_uint2(pkh(v1.x*inv, v1.y*inv), pkh(v1.z*inv, v1.w*inv));
    if (hraw) {
        uint2* ur = reinterpret_cast<uint2*>(hraw);
        ur[lane]      = make_uint2(pkh(v0.x, v0.y), pkh(v0.z, v0.w));
        ur[lane + 32] = make_uint2(pkh(v1.x, v1.y), pkh(v1.z, v1.w));
    }
}

// ---------------- logits GEMM: cos = Ahat @ Bhat^T --------------------------
// Normalized fp16 operands via cp.async double-buffer, single sync/iter.
// BM=128, BN=128, BK=64, 256 thr, 8 warps 4(m)x2(n). blockIdx.z = which.
// Epilogue: write cos f32; write P'=exp(cos+8) fp16 to g_P; quad-reduced
// partial sumexp -> g_partial[row][bn*2+wn].
__global__ __launch_bounds__(256) void logits_kernel(
    float* __restrict__ out0, float* __restrict__ out1, int N, int S)
{
    extern __shared__ __align__(16) char sm[];
    __half* As = (__half*)sm;              // [2][128][72]
    __half* Bs = (__half*)(sm + 36864);    // [2][128][72]
    const int which = blockIdx.z;
    float* out = which ? out1 : out0;
    const __half* A = which ? g_fa_h : g_sp_h;
    const __half* B = which ? g_fkmn_h : g_svmn_h;
    const int naoff = which ? N : 0;
    const int tid = threadIdx.x;
    const int warp = tid >> 5, lane = tid & 31;
    const int wm = warp >> 1, wn = warp & 1;
    const long bm = blockIdx.y, bn = blockIdx.x;
    const __half* Ab = A + bm * 128 * 256;
    const __half* Bb = B + bn * 128 * 256;
    uint32_t sa = (uint32_t)__cvta_generic_to_shared(As);
    uint32_t sb = (uint32_t)__cvta_generic_to_shared(Bs);
    const int lr = tid >> 3, lc = (tid & 7) * 8;

    float acc[2][8][4] = {};

    // prologue: stage 0
    #pragma unroll
    for (int i = 0; i < 4; i++) {
        int r = lr + i * 32;
        cpa16(sa + (unsigned)(r * 72 + lc) * 2, Ab + r * 256 + lc);
        cpa16(sb + (unsigned)(r * 72 + lc) * 2, Bb + r * 256 + lc);
    }
    CP_COMMIT;

    for (int kb = 0; kb < 4; ++kb) {
        CP_WAIT(0);
        __syncthreads();
        if (kb < 3) {
            int st = (kb + 1) & 1;
            #pragma unroll
            for (int i = 0; i < 4; i++) {
                int r = lr + i * 32;
                cpa16(sa + (unsigned)(st * 9216 + r * 72 + lc) * 2, Ab + r * 256 + (kb + 1) * 64 + lc);
                cpa16(sb + (unsigned)(st * 9216 + r * 72 + lc) * 2, Bb + r * 256 + (kb + 1) * 64 + lc);
            }
            CP_COMMIT;
        }
        const __half* Ast = As + (kb & 1) * 9216;
        const __half* Bst = Bs + (kb & 1) * 9216;
        #pragma unroll
        for (int kk = 0; kk < 4; ++kk) {
            unsigned a[2][4], b[4][4];
            #pragma unroll
            for (int mt = 0; mt < 2; ++mt) {
                int r = wm * 32 + mt * 16 + (lane & 15);
                int c = kk * 16 + ((lane >> 4) << 3);
                ldsm4(a[mt], Ast + r * 72 + c);
            }
            #pragma unroll
            for (int np = 0; np < 4; ++np) {
                int g = lane >> 3;
                int r = wn * 64 + np * 16 + ((g >> 1) << 3) + (lane & 7);
                int c = kk * 16 + ((g & 1) << 3);
                ldsm4(b[np], Bst + r * 72 + c);
            }
            #pragma unroll
            for (int mt = 0; mt < 2; ++mt)
                #pragma unroll
                for (int nt = 0; nt < 8; ++nt)
                    mma16816(acc[mt][nt], a[mt], b[nt >> 1][(nt & 1) * 2], b[nt >> 1][(nt & 1) * 2 + 1]);
        }
    }

    #pragma unroll
    for (int mt = 0; mt < 2; ++mt) {
        int r = (int)(bm * 128) + wm * 32 + mt * 16 + (lane >> 2);
        float ps0 = 0.f, ps1 = 0.f;
        #pragma unroll
        for (int nt = 0; nt < 8; ++nt) {
            int c = (int)(bn * 128) + wn * 64 + nt * 8 + (lane & 3) * 2;
            float c00 = acc[mt][nt][0], c01 = acc[mt][nt][1];
            float c10 = acc[mt][nt][2], c11 = acc[mt][nt][3];
            float e00 = __expf(c00), e01 = __expf(c01);
            float e10 = __expf(c10), e11 = __expf(c11);
            ps0 += e00 + e01;
            ps1 += e10 + e11;
            *reinterpret_cast<float2*>(out + (long)r * S + c) = make_float2(c00, c01);
            *reinterpret_cast<float2*>(out + (long)(r + 8) * S + c) = make_float2(c10, c11);
            *reinterpret_cast<unsigned*>(&g_P[(long)(naoff + r) * S + c]) = pkh(e00 * E8F, e01 * E8F);
            *reinterpret_cast<unsigned*>(&g_P[(long)(naoff + r + 8) * S + c]) = pkh(e10 * E8F, e11 * E8F);
        }
        ps0 += __shfl_xor_sync(0xffffffffu, ps0, 1);
        ps0 += __shfl_xor_sync(0xffffffffu, ps0, 2);
        ps1 += __shfl_xor_sync(0xffffffffu, ps1, 1);
        ps1 += __shfl_xor_sync(0xffffffffu, ps1, 2);
        if ((lane & 3) == 0) {
            int chunk = (int)bn * 2 + wn;
            g_partial[(long)(naoff + r) * 64 + chunk] = ps0;
            g_partial[(long)(naoff + r + 8) * 64 + chunk] = ps1;
        }
    }
}

// ---------------- recall GEMM (pure fp16) + addr_log stream ----------------
// P' and V tiles via cp.async (2 stages, ONE sync/iter). Softmax scale in
// epilogue: recall_row = (exp(-8)/sumexp_row) * (P' @ V)_row.
// addr_log = cos - lse streamed via __ldcs/__stcs (register-only, overlapped).
// BM=64, BN=256, BK=64, 256 thr, warps 2(m)x4(n). blockIdx.y = which.
__global__ __launch_bounds__(256) void recall_kernel(
    float* __restrict__ logits0, float* __restrict__ logits1,
    float* __restrict__ outR0, float* __restrict__ outR1, int N, int S)
{
    extern __shared__ __align__(16) char sm[];
    __half* Vs = (__half*)sm;                  // [2][64][264]
    __half* Ps = (__half*)(sm + 67584);        // [2][64][72]
    float*  Ls = (float*)(sm + 86016);         // 64: lse
    float*  Si = (float*)(sm + 86272);         // 64: exp(-8)/sumexp
    const __half* V = g_svm_h;   // both recalls use raw speech_value_memory
    const int which = blockIdx.y;
    float* logits = which ? logits1 : logits0;
    float* outR   = which ? outR1   : outR0;
    const int lseoff = which ? N : 0;
    const int tid = threadIdx.x;
    const int warp = tid >> 5, lane = tid & 31;
    const int wm = warp >> 2, wn = warp & 3;
    const long bm = blockIdx.x;
    float* Lg = logits + bm * 64 * (long)S;
    const __half* Pg = g_P + (long)(lseoff + bm * 64) * S;
    uint32_t sv = (uint32_t)__cvta_generic_to_shared(Vs);
    uint32_t sp = (uint32_t)__cvta_generic_to_shared(Ps);

    if (tid < 64) {
        const float4* pp = reinterpret_cast<const float4*>(g_partial + (long)(lseoff + bm * 64 + tid) * 64);
        float s = 0.f;
        #pragma unroll
        for (int j = 0; j < 16; j++) { float4 v = pp[j]; s += v.x + v.y + v.z + v.w; }
        Ls[tid] = logf(s);
        Si[tid] = PSCALE / s;
    }

    float acc[2][8][4] = {};

    // prologue: stage 0
    #pragma unroll
    for (int i = 0; i < 8; i++) {
        int idx = tid + i * 256, r = idx >> 5, c = idx & 31;
        cpa16(sv + (unsigned)(r * 264 + c * 8) * 2, V + (long)r * 256 + c * 8);
    }
    #pragma unroll
    for (int i = 0; i < 2; i++) {
        int idx = tid + i * 256, r = idx >> 3, c8 = (idx & 7) * 8;
        cpa16(sp + (unsigned)(r * 72 + c8) * 2, Pg + (long)r * S + c8);
    }
    CP_COMMIT;

    const int KB = S / 64;
    for (int kb = 0; kb < KB; ++kb) {
        CP_WAIT(0);
        __syncthreads();
        if (kb < KB - 1) {
            int st = (kb + 1) & 1;
            #pragma unroll
            for (int i = 0; i < 8; i++) {
                int idx = tid + i * 256, r = idx >> 5, c = idx & 31;
                cpa16(sv + (unsigned)(st * 16896 + r * 264 + c * 8) * 2,
                      V + (long)((kb + 1) * 64 + r) * 256 + c * 8);
            }
            #pragma unroll
            for (int i = 0; i < 2; i++) {
                int idx = tid + i * 256, r = idx >> 3, c8 = (idx & 7) * 8;
                cpa16(sp + (unsigned)(st * 4608 + r * 72 + c8) * 2,
                      Pg + (long)r * S + (kb + 1) * 64 + c8);
            }
            CP_COMMIT;
        }
        // addr_log stream: issue loads now, consume after mma
        float4 cv[4];
        #pragma unroll
        for (int i = 0; i < 4; i++) {
            int idx = tid + i * 256, r = idx >> 4, c4 = idx & 15;
            cv[i] = __ldcs(reinterpret_cast<const float4*>(Lg + (long)r * S + kb * 64 + c4 * 4));
        }

        const int st = kb & 1;
        const __half* Pst = Ps + st * 4608;
        const __half* Vst = Vs + st * 16896;
        #pragma unroll
        for (int kk = 0; kk < 4; ++kk) {
            unsigned a[2][4], b[4][4];
            #pragma unroll
            for (int mt = 0; mt < 2; ++mt) {
                int r = wm * 32 + mt * 16 + (lane & 15);
                int c = kk * 16 + ((lane >> 4) << 3);
                ldsm4(a[mt], Pst + r * 72 + c);
            }
            #pragma unroll
            for (int np = 0; np < 4; ++np) {   // V rows=k, cols=n -> trans
                int g = lane >> 3;
                int r = kk * 16 + ((g & 1) << 3) + (lane & 7);
                int c = wn * 64 + np * 16 + ((g >> 1) << 3);
                ldsm4t(b[np], Vst + r * 264 + c);
            }
            #pragma unroll
            for (int mt = 0; mt < 2; ++mt)
                #pragma unroll
                for (int nt = 0; nt < 8; ++nt)
                    mma16816(acc[mt][nt], a[mt], b[nt >> 1][(nt & 1) * 2], b[nt >> 1][(nt & 1) * 2 + 1]);
        }

        // finish addr_log stream
        #pragma unroll
        for (int i = 0; i < 4; i++) {
            int idx = tid + i * 256, r = idx >> 4, c4 = idx & 15;
            float l = Ls[r];
            float4 v = cv[i];
            v.x -= l; v.y -= l; v.z -= l; v.w -= l;
            __stcs(reinterpret_cast<float4*>(Lg + (long)r * S + kb * 64 + c4 * 4), v);
        }
    }

    #pragma unroll
    for (int mt = 0; mt < 2; ++mt) {
        int rl = wm * 32 + mt * 16 + (lane >> 2);
        int r = (int)(bm * 64) + rl;
        float s0 = Si[rl], s1 = Si[rl + 8];
        #pragma unroll
        for (int nt = 0; nt < 8; ++nt) {
            int c = wn * 64 + nt * 8 + (lane & 3) * 2;
            *reinterpret_cast<float2*>(outR + (long)r * 256 + c) =
                make_float2(acc[mt][nt][0] * s0, acc[mt][nt][1] * s0);
            *reinterpret_cast<float2*>(outR + (long)(r + 8) * 256 + c) =
                make_float2(acc[mt][nt][2] * s1, acc[mt][nt][3] * s1);
        }
    }
}

// ---------------------------------------------------------------------------
static const int LOG_SMEM = 73728;
static const int REC_SMEM = 86528;

extern "C" void kernel_launch(void* const* d_in, const int* in_sizes, int n_in,
                              void* d_out, int out_size) {
    const float* face   = (const float*)d_in[0];
    const float* speech = (const float*)d_in[1];
    const float* svm    = (const float*)d_in[2];
    const float* fkm    = (const float*)d_in[3];
    const int C = 256;
    const int N = in_sizes[0] / C;   // 8192
    const int S = in_sizes[2] / C;   // 4096
    float* out = (float*)d_out;
    const long NC = (long)N * C;
    const long NS = (long)N * S;

    float* o_srec = out + NC;          // speech_emb_recall
    float* o_frec = out + 3 * NC;      // face_emb_recall
    float* o_slog = out + 4 * NC;      // speech_address_log (holds raw cos first)
    float* o_flog = out + 4 * NC + NS; // face_address_log

    cudaFuncSetAttribute(logits_kernel, cudaFuncAttributeMaxDynamicSharedMemorySize, LOG_SMEM);
    cudaFuncSetAttribute(recall_kernel, cudaFuncAttributeMaxDynamicSharedMemorySize, REC_SMEM);

    // identity embeddings
    cudaMemcpyAsync(out,          speech, NC * sizeof(float), cudaMemcpyDeviceToDevice, 0);
    cudaMemcpyAsync(out + 2 * NC, face,   NC * sizeof(float), cudaMemcpyDeviceToDevice, 0);

    int rows = 2 * N + 2 * S;
    convert_norms_kernel<<<(rows + 7) / 8, 256>>>(face, speech, svm, fkm, N, S);

    dim3 g2(S / 128, N / 128, 2);
    logits_kernel<<<g2, 256, LOG_SMEM>>>(o_slog, o_flog, N, S);

    dim3 g3(N / 64, 2);
    recall_kernel<<<g3, 256, REC_SMEM>>>(o_slog, o_flog, o_srec, o_frec, N, S);
}

// round 11
// speedup vs baseline: 1.1988x; 1.1988x over previous
#include <cuda_runtime.h>
#include <cuda_fp16.h>
#include <cstdint>

#define CEPS 1e-8f
#define PSHIFT 8.0f
#define PSCALE 0.000335462627902512f  // exp(-8)

// scratch (N<=8192, S<=4096 for this problem)
static __device__ float g_norm_emb[16384]; // speech rows [0,N), face rows [N,2N)
static __device__ float g_norm_mem[8192];  // svm rows [0,S), fkm rows [S,2S)
static __device__ float g_partial[16384 * 64]; // per-row partial sumexp (64 chunks/row)
static __device__ __half g_sp_h[8192 * 256];
static __device__ __half g_fa_h[8192 * 256];
static __device__ __half g_svm_h[4096 * 256];
static __device__ __half g_fkm_h[4096 * 256];

__device__ __forceinline__ unsigned pkh(float a, float b){
    __half2 h = __floats2half2_rn(a, b);
    return *reinterpret_cast<unsigned*>(&h);
}
__device__ __forceinline__ void cpa16(uint32_t dst, const void* src){
    asm volatile("cp.async.cg.shared.global [%0], [%1], 16;\n" :: "r"(dst), "l"(src));
}
#define CP_COMMIT asm volatile("cp.async.commit_group;\n" ::: "memory")
#define CP_WAIT(n) asm volatile("cp.async.wait_group %0;\n" :: "n"(n) : "memory")

__device__ __forceinline__ void ldsm4(unsigned r[4], const void* p){
    uint32_t a = (uint32_t)__cvta_generic_to_shared(p);
    asm volatile("ldmatrix.sync.aligned.m8n8.x4.shared.b16 {%0,%1,%2,%3}, [%4];\n"
        : "=r"(r[0]), "=r"(r[1]), "=r"(r[2]), "=r"(r[3]) : "r"(a));
}
__device__ __forceinline__ void ldsm4t(unsigned r[4], const void* p){
    uint32_t a = (uint32_t)__cvta_generic_to_shared(p);
    asm volatile("ldmatrix.sync.aligned.m8n8.x4.trans.shared.b16 {%0,%1,%2,%3}, [%4];\n"
        : "=r"(r[0]), "=r"(r[1]), "=r"(r[2]), "=r"(r[3]) : "r"(a));
}
// f32 accumulate (recall)
__device__ __forceinline__ void mma16816(float c[4], const unsigned a[4], unsigned b0, unsigned b1){
    asm volatile("mma.sync.aligned.m16n8k16.row.col.f32.f16.f16.f32 "
        "{%0,%1,%2,%3}, {%4,%5,%6,%7}, {%8,%9}, {%0,%1,%2,%3};\n"
        : "+f"(c[0]), "+f"(c[1]), "+f"(c[2]), "+f"(c[3])
        : "r"(a[0]), "r"(a[1]), "r"(a[2]), "r"(a[3]), "r"(b0), "r"(b1));
}
// f16 accumulate (logits) — c[0]=(row, col|col+1) f16x2, c[1]=(row+8, ...)
__device__ __forceinline__ void mma16816h(unsigned c[2], const unsigned a[4], unsigned b0, unsigned b1){
    asm volatile("mma.sync.aligned.m16n8k16.row.col.f16.f16.f16.f16 "
        "{%0,%1}, {%2,%3,%4,%5}, {%6,%7}, {%0,%1};\n"
        : "+r"(c[0]), "+r"(c[1])
        : "r"(a[0]), "r"(a[1]), "r"(a[2]), "r"(a[3]), "r"(b0), "r"(b1));
}

// ------------- fused convert(f32->f16) + row norms: one warp per row -------
__global__ void convert_norms_kernel(const float* __restrict__ face, const float* __restrict__ speech,
                                     const float* __restrict__ svm, const float* __restrict__ fkm,
                                     int N, int S){
    int warp = threadIdx.x >> 5, lane = threadIdx.x & 31;
    int rid = blockIdx.x * 8 + warp;
    int total = 2*N + 2*S;
    if (rid >= total) return;
    const float* src; float* ndst; __half* hdst;
    if (rid < N)            { src = speech + (long)rid * 256; ndst = g_norm_emb + rid; hdst = g_sp_h + (long)rid * 256; }
    else if (rid < 2*N)     { int r = rid - N; src = face + (long)r * 256; ndst = g_norm_emb + rid; hdst = g_fa_h + (long)r * 256; }
    else if (rid < 2*N + S) { int r = rid - 2*N; src = svm + (long)r * 256; ndst = g_norm_mem + r; hdst = g_svm_h + (long)r * 256; }
    else                    { int r = rid - 2*N - S; src = fkm + (long)r * 256; ndst = g_norm_mem + (rid - 2*N); hdst = g_fkm_h + (long)r * 256; }
    const float4* p = reinterpret_cast<const float4*>(src);
    float4 v0 = p[lane], v1 = p[lane + 32];
    uint2* up = reinterpret_cast<uint2*>(hdst);
    up[lane]      = make_uint2(pkh(v0.x, v0.y), pkh(v0.z, v0.w));
    up[lane + 32] = make_uint2(pkh(v1.x, v1.y), pkh(v1.z, v1.w));
    float s = v0.x*v0.x + v0.y*v0.y + v0.z*v0.z + v0.w*v0.w
            + v1.x*v1.x + v1.y*v1.y + v1.z*v1.z + v1.w*v1.w;
    #pragma unroll
    for (int o = 16; o; o >>= 1) s += __shfl_xor_sync(0xffffffffu, s, o);
    if (lane == 0) *ndst = sqrtf(s);
}

// ---------------- logits GEMM: cos = (A@B^T)/max(|a||b|,eps) ----------------
// fp16 operands + FP16 ACCUMULATE (2x HMMA rate if pipe supports it).
// BM=128, BN=128, BK=64, 256 thr, 8 warps 4(m)x2(n). blockIdx.z = which.
// Fused lse: per-thread sum(exp(cos)), quad-reduced -> g_partial.
__global__ __launch_bounds__(256) void logits_kernel(
    float* __restrict__ out0, float* __restrict__ out1, int N, int S)
{
    extern __shared__ __align__(16) char sm[];
    __half* As = (__half*)sm;              // [2][128][72]
    __half* Bs = (__half*)(sm + 36864);    // [2][128][72]
    const int which = blockIdx.z;
    float* out = which ? out1 : out0;
    const __half* A = which ? g_fa_h : g_sp_h;
    const __half* B = which ? g_fkm_h : g_svm_h;
    const int naoff = which ? N : 0, nboff = which ? S : 0;
    const int tid = threadIdx.x;
    const int warp = tid >> 5, lane = tid & 31;
    const int wm = warp >> 1, wn = warp & 1;
    const long bm = blockIdx.y, bn = blockIdx.x;
    const __half* Ab = A + bm * 128 * 256;
    const __half* Bb = B + bn * 128 * 256;
    uint32_t sa = (uint32_t)__cvta_generic_to_shared(As);
    uint32_t sb = (uint32_t)__cvta_generic_to_shared(Bs);
    const int lr = tid >> 3, lc = (tid & 7) * 8;   // chunk: 8 halves

    unsigned acc[2][8][2] = {};   // f16x2 accumulators

    // prologue: stage 0
    #pragma unroll
    for (int i = 0; i < 4; i++) {
        int r = lr + i * 32;
        cpa16(sa + (unsigned)(r * 72 + lc) * 2, Ab + r * 256 + lc);
        cpa16(sb + (unsigned)(r * 72 + lc) * 2, Bb + r * 256 + lc);
    }
    CP_COMMIT;

    for (int kb = 0; kb < 4; ++kb) {
        if (kb < 3) {
            int st = (kb + 1) & 1;
            #pragma unroll
            for (int i = 0; i < 4; i++) {
                int r = lr + i * 32;
                cpa16(sa + (unsigned)(st * 9216 + r * 72 + lc) * 2, Ab + r * 256 + (kb + 1) * 64 + lc);
                cpa16(sb + (unsigned)(st * 9216 + r * 72 + lc) * 2, Bb + r * 256 + (kb + 1) * 64 + lc);
            }
        }
        CP_COMMIT;
        CP_WAIT(1);
        __syncthreads();
        const __half* Ast = As + (kb & 1) * 9216;
        const __half* Bst = Bs + (kb & 1) * 9216;
        #pragma unroll
        for (int kk = 0; kk < 4; ++kk) {
            unsigned a[2][4], b[4][4];
            #pragma unroll
            for (int mt = 0; mt < 2; ++mt) {
                int r = wm * 32 + mt * 16 + (lane & 15);
                int c = kk * 16 + ((lane >> 4) << 3);
                ldsm4(a[mt], Ast + r * 72 + c);
            }
            #pragma unroll
            for (int np = 0; np < 4; ++np) {
                int g = lane >> 3;
                int r = wn * 64 + np * 16 + ((g >> 1) << 3) + (lane & 7);
                int c = kk * 16 + ((g & 1) << 3);
                ldsm4(b[np], Bst + r * 72 + c);
            }
            #pragma unroll
            for (int mt = 0; mt < 2; ++mt)
                #pragma unroll
                for (int nt = 0; nt < 8; ++nt)
                    mma16816h(acc[mt][nt], a[mt], b[nt >> 1][(nt & 1) * 2], b[nt >> 1][(nt & 1) * 2 + 1]);
        }
        __syncthreads();
    }

    #pragma unroll
    for (int mt = 0; mt < 2; ++mt) {
        int r = (int)(bm * 128) + wm * 32 + mt * 16 + (lane >> 2);
        float na0 = g_norm_emb[naoff + r];
        float na1 = g_norm_emb[naoff + r + 8];
        float ps0 = 0.f, ps1 = 0.f;
        #pragma unroll
        for (int nt = 0; nt < 8; ++nt) {
            int c = (int)(bn * 128) + wn * 64 + nt * 8 + (lane & 3) * 2;
            float nb0 = g_norm_mem[nboff + c];
            float nb1 = g_norm_mem[nboff + c + 1];
            float2 f0 = __half22float2(*reinterpret_cast<__half2*>(&acc[mt][nt][0]));
            float2 f1 = __half22float2(*reinterpret_cast<__half2*>(&acc[mt][nt][1]));
            float c00 = f0.x / fmaxf(na0 * nb0, CEPS);
            float c01 = f0.y / fmaxf(na0 * nb1, CEPS);
            float c10 = f1.x / fmaxf(na1 * nb0, CEPS);
            float c11 = f1.y / fmaxf(na1 * nb1, CEPS);
            ps0 += __expf(c00) + __expf(c01);
            ps1 += __expf(c10) + __expf(c11);
            *reinterpret_cast<float2*>(out + (long)r * S + c) = make_float2(c00, c01);
            *reinterpret_cast<float2*>(out + (long)(r + 8) * S + c) = make_float2(c10, c11);
        }
        // quad reduction (lanes differing in bits 0,1 share the same rows)
        ps0 += __shfl_xor_sync(0xffffffffu, ps0, 1);
        ps0 += __shfl_xor_sync(0xffffffffu, ps0, 2);
        ps1 += __shfl_xor_sync(0xffffffffu, ps1, 1);
        ps1 += __shfl_xor_sync(0xffffffffu, ps1, 2);
        if ((lane & 3) == 0) {
            int chunk = (int)bn * 2 + wn;
            g_partial[(long)(naoff + r) * 64 + chunk] = ps0;
            g_partial[(long)(naoff + r + 8) * 64 + chunk] = ps1;
        }
    }
}

// ---------------- recall GEMM + address_log finalize ----------------------
// blockIdx.y selects speech/face (merged launch). Ls = log(sum of 64
// partials, fixed order). out_addr_log = logit - lse (written back);
// P' = exp(.+8) fp16; recall = exp(-8) * (P' @ svm). BM=64, BN=256, BK=64.
__global__ __launch_bounds__(256) void recall_kernel(
    float* __restrict__ logits0, float* __restrict__ logits1,
    float* __restrict__ outR0, float* __restrict__ outR1, int N, int S)
{
    extern __shared__ __align__(16) char sm[];
    __half* Vs = (__half*)sm;                        // [2][64][264]
    float*  Lf = (float*)(sm + 67584);               // [2][64][68]
    __half* Ps = (__half*)(sm + 67584 + 34816);      // [2][64][72]
    float*  Ls = (float*)(sm + 67584 + 34816 + 18432);
    const __half* V = g_svm_h;   // both recalls use speech_value_memory
    const int which = blockIdx.y;
    float* logits = which ? logits1 : logits0;
    float* outR   = which ? outR1   : outR0;
    const int lseoff = which ? N : 0;
    const int tid = threadIdx.x;
    const int warp = tid >> 5, lane = tid & 31;
    const int wm = warp >> 2, wn = warp & 3;
    const long bm = blockIdx.x;
    float* Lg = logits + bm * 64 * (long)S;
    uint32_t sv = (uint32_t)__cvta_generic_to_shared(Vs);
    uint32_t sl = (uint32_t)__cvta_generic_to_shared(Lf);

    if (tid < 64) {
        const float4* pp = reinterpret_cast<const float4*>(g_partial + (long)(lseoff + bm * 64 + tid) * 64);
        float s = 0.f;
        #pragma unroll
        for (int j = 0; j < 16; j++) { float4 v = pp[j]; s += v.x + v.y + v.z + v.w; }
        Ls[tid] = logf(s);
    }

    float acc[2][8][4] = {};

    // prologue loads stage 0
    #pragma unroll
    for (int i = 0; i < 8; i++) {
        int idx = tid + i * 256, r = idx >> 5, c = idx & 31;
        cpa16(sv + (unsigned)(r * 264 + c * 8) * 2, V + (long)r * 256 + c * 8);
    }
    #pragma unroll
    for (int i = 0; i < 4; i++) {
        int idx = tid + i * 256, r = idx >> 4, c = idx & 15;
        cpa16(sl + (unsigned)(r * 68 + c * 4) * 4, Lg + (long)r * S + c * 4);
    }
    CP_COMMIT;

    const int KB = S / 64;
    for (int kb = 0; kb < KB; ++kb) {
        CP_WAIT(0);
        __syncthreads();
        if (kb < KB - 1) {
            int st = (kb + 1) & 1;
            #pragma unroll
            for (int i = 0; i < 8; i++) {
                int idx = tid + i * 256, r = idx >> 5, c = idx & 31;
                cpa16(sv + (unsigned)(st * 16896 + r * 264 + c * 8) * 2,
                      V + (long)((kb + 1) * 64 + r) * 256 + c * 8);
            }
            #pragma unroll
            for (int i = 0; i < 4; i++) {
                int idx = tid + i * 256, r = idx >> 4, c = idx & 15;
                cpa16(sl + (unsigned)(st * 4352 + r * 68 + c * 4) * 4,
                      Lg + (long)r * S + (kb + 1) * 64 + c * 4);
            }
            CP_COMMIT;
        }
        const int st = kb & 1;
        // build Ps from Lf + writeback address_log
        #pragma unroll
        for (int i = 0; i < 4; i++) {
            int idx = tid + i * 256, r = idx >> 4, c = idx & 15;
            float4 v = *reinterpret_cast<float4*>(Lf + st * 4352 + r * 68 + c * 4);
            float l = Ls[r];
            v.x -= l; v.y -= l; v.z -= l; v.w -= l;
            *reinterpret_cast<float4*>(Lg + (long)r * S + kb * 64 + c * 4) = v;
            *reinterpret_cast<uint2*>(Ps + st * 4608 + r * 72 + c * 4) =
                make_uint2(pkh(__expf(v.x + PSHIFT), __expf(v.y + PSHIFT)),
                           pkh(__expf(v.z + PSHIFT), __expf(v.w + PSHIFT)));
        }
        __syncthreads();
        const __half* Pst = Ps + st * 4608;
        const __half* Vst = Vs + st * 16896;
        #pragma unroll
        for (int kk = 0; kk < 4; ++kk) {
            unsigned a[2][4], b[4][4];
            #pragma unroll
            for (int mt = 0; mt < 2; ++mt) {
                int r = wm * 32 + mt * 16 + (lane & 15);
                int c = kk * 16 + ((lane >> 4) << 3);
                ldsm4(a[mt], Pst + r * 72 + c);
            }
            #pragma unroll
            for (int np = 0; np < 4; ++np) {   // V rows=k, cols=n -> trans
                int g = lane >> 3;
                int r = kk * 16 + ((g & 1) << 3) + (lane & 7);
                int c = wn * 64 + np * 16 + ((g >> 1) << 3);
                ldsm4t(b[np], Vst + r * 264 + c);
            }
            #pragma unroll
            for (int mt = 0; mt < 2; ++mt)
                #pragma unroll
                for (int nt = 0; nt < 8; ++nt)
                    mma16816(acc[mt][nt], a[mt], b[nt >> 1][(nt & 1) * 2], b[nt >> 1][(nt & 1) * 2 + 1]);
        }
        __syncthreads();
    }

    #pragma unroll
    for (int mt = 0; mt < 2; ++mt) {
        int r = (int)(bm * 64) + wm * 32 + mt * 16 + (lane >> 2);
        #pragma unroll
        for (int nt = 0; nt < 8; ++nt) {
            int c = wn * 64 + nt * 8 + (lane & 3) * 2;
            *reinterpret_cast<float2*>(outR + (long)r * 256 + c) =
                make_float2(acc[mt][nt][0] * PSCALE, acc[mt][nt][1] * PSCALE);
            *reinterpret_cast<float2*>(outR + (long)(r + 8) * 256 + c) =
                make_float2(acc[mt][nt][2] * PSCALE, acc[mt][nt][3] * PSCALE);
        }
    }
}

// ---------------------------------------------------------------------------
static const int LOG_SMEM = 73728;
static const int REC_SMEM = 67584 + 34816 + 18432 + 256;

extern "C" void kernel_launch(void* const* d_in, const int* in_sizes, int n_in,
                              void* d_out, int out_size) {
    const float* face   = (const float*)d_in[0];
    const float* speech = (const float*)d_in[1];
    const float* svm    = (const float*)d_in[2];
    const float* fkm    = (const float*)d_in[3];
    const int C = 256;
    const int N = in_sizes[0] / C;   // 8192
    const int S = in_sizes[2] / C;   // 4096
    float* out = (float*)d_out;
    const long NC = (long)N * C;
    const long NS = (long)N * S;

    float* o_srec = out + NC;          // speech_emb_recall
    float* o_frec = out + 3 * NC;      // face_emb_recall
    float* o_slog = out + 4 * NC;      // speech_address_log (holds raw cos first)
    float* o_flog = out + 4 * NC + NS; // face_address_log

    cudaFuncSetAttribute(logits_kernel, cudaFuncAttributeMaxDynamicSharedMemorySize, LOG_SMEM);
    cudaFuncSetAttribute(recall_kernel, cudaFuncAttributeMaxDynamicSharedMemorySize, REC_SMEM);

    // identity embeddings
    cudaMemcpyAsync(out,          speech, NC * sizeof(float), cudaMemcpyDeviceToDevice, 0);
    cudaMemcpyAsync(out + 2 * NC, face,   NC * sizeof(float), cudaMemcpyDeviceToDevice, 0);

    int rows = 2 * N + 2 * S;
    convert_norms_kernel<<<(rows + 7) / 8, 256>>>(face, speech, svm, fkm, N, S);

    dim3 g2(S / 128, N / 128, 2);
    logits_kernel<<<g2, 256, LOG_SMEM>>>(o_slog, o_flog, N, S);

    dim3 g3(N / 64, 2);
    recall_kernel<<<g3, 256, REC_SMEM>>>(o_slog, o_flog, o_srec, o_frec, N, S);
}

// round 13
// speedup vs baseline: 1.2608x; 1.0517x over previous
#include <cuda_runtime.h>
#include <cuda_fp16.h>
#include <cstdint>

#define PSHIFT 8.0f
#define PSCALE 0.000335462627902512f  // exp(-8)

// scratch (N<=8192, S<=4096 for this problem)
static __device__ float g_partial[16384 * 64]; // per-row partial sumexp (64 chunks/row)
static __device__ __half g_sp_h[8192 * 256];   // normalized speech
static __device__ __half g_fa_h[8192 * 256];   // normalized face
static __device__ __half g_svmn_h[4096 * 256]; // normalized svm (logits B)
static __device__ __half g_fkmn_h[4096 * 256]; // normalized fkm (logits B)
static __device__ __half g_svm_h[4096 * 256];  // RAW svm (recall V)

__device__ __forceinline__ unsigned pkh(float a, float b){
    __half2 h = __floats2half2_rn(a, b);
    return *reinterpret_cast<unsigned*>(&h);
}
__device__ __forceinline__ void cpa16(uint32_t dst, const void* src){
    asm volatile("cp.async.cg.shared.global [%0], [%1], 16;\n" :: "r"(dst), "l"(src));
}
#define CP_COMMIT asm volatile("cp.async.commit_group;\n" ::: "memory")
#define CP_WAIT(n) asm volatile("cp.async.wait_group %0;\n" :: "n"(n) : "memory")

__device__ __forceinline__ void ldsm4(unsigned r[4], const void* p){
    uint32_t a = (uint32_t)__cvta_generic_to_shared(p);
    asm volatile("ldmatrix.sync.aligned.m8n8.x4.shared.b16 {%0,%1,%2,%3}, [%4];\n"
        : "=r"(r[0]), "=r"(r[1]), "=r"(r[2]), "=r"(r[3]) : "r"(a));
}
__device__ __forceinline__ void ldsm4t(unsigned r[4], const void* p){
    uint32_t a = (uint32_t)__cvta_generic_to_shared(p);
    asm volatile("ldmatrix.sync.aligned.m8n8.x4.trans.shared.b16 {%0,%1,%2,%3}, [%4];\n"
        : "=r"(r[0]), "=r"(r[1]), "=r"(r[2]), "=r"(r[3]) : "r"(a));
}
// f32 accumulate (recall)
__device__ __forceinline__ void mma16816(float c[4], const unsigned a[4], unsigned b0, unsigned b1){
    asm volatile("mma.sync.aligned.m16n8k16.row.col.f32.f16.f16.f32 "
        "{%0,%1,%2,%3}, {%4,%5,%6,%7}, {%8,%9}, {%0,%1,%2,%3};\n"
        : "+f"(c[0]), "+f"(c[1]), "+f"(c[2]), "+f"(c[3])
        : "r"(a[0]), "r"(a[1]), "r"(a[2]), "r"(a[3]), "r"(b0), "r"(b1));
}
// f16 accumulate (logits)
__device__ __forceinline__ void mma16816h(unsigned c[2], const unsigned a[4], unsigned b0, unsigned b1){
    asm volatile("mma.sync.aligned.m16n8k16.row.col.f16.f16.f16.f16 "
        "{%0,%1}, {%2,%3,%4,%5}, {%6,%7}, {%0,%1};\n"
        : "+r"(c[0]), "+r"(c[1])
        : "r"(a[0]), "r"(a[1]), "r"(a[2]), "r"(a[3]), "r"(b0), "r"(b1));
}

// ------- fused convert + normalize + identity-embedding copy ---------------
// one warp per row; writes normalized fp16 operands; for svm also raw fp16;
// for speech/face also the f32 identity embedding into the output buffer.
__global__ void convert_norms_kernel(const float* __restrict__ face, const float* __restrict__ speech,
                                     const float* __restrict__ svm, const float* __restrict__ fkm,
                                     float* __restrict__ out_se, float* __restrict__ out_fe,
                                     int N, int S){
    int warp = threadIdx.x >> 5, lane = threadIdx.x & 31;
    int rid = blockIdx.x * 8 + warp;
    int total = 2*N + 2*S;
    if (rid >= total) return;
    const float* src; __half* hdst; __half* hraw = nullptr; float* fcopy = nullptr;
    if (rid < N)            { src = speech + (long)rid * 256; hdst = g_sp_h + (long)rid * 256;
                              fcopy = out_se + (long)rid * 256; }
    else if (rid < 2*N)     { int r = rid - N; src = face + (long)r * 256; hdst = g_fa_h + (long)r * 256;
                              fcopy = out_fe + (long)r * 256; }
    else if (rid < 2*N + S) { int r = rid - 2*N; src = svm + (long)r * 256;
                              hdst = g_svmn_h + (long)r * 256; hraw = g_svm_h + (long)r * 256; }
    else                    { int r = rid - 2*N - S; src = fkm + (long)r * 256; hdst = g_fkmn_h + (long)r * 256; }
    const float4* p = reinterpret_cast<const float4*>(src);
    float4 v0 = p[lane], v1 = p[lane + 32];
    float s = v0.x*v0.x + v0.y*v0.y + v0.z*v0.z + v0.w*v0.w
            + v1.x*v1.x + v1.y*v1.y + v1.z*v1.z + v1.w*v1.w;
    #pragma unroll
    for (int o = 16; o; o >>= 1) s += __shfl_xor_sync(0xffffffffu, s, o);
    float inv = rsqrtf(s);
    uint2* up = reinterpret_cast<uint2*>(hdst);
    up[lane]      = make_uint2(pkh(v0.x*inv, v0.y*inv), pkh(v0.z*inv, v0.w*inv));
    up[lane + 32] = make_uint2(pkh(v1.x*inv, v1.y*inv), pkh(v1.z*inv, v1.w*inv));
    if (hraw) {
        uint2* ur = reinterpret_cast<uint2*>(hraw);
        ur[lane]      = make_uint2(pkh(v0.x, v0.y), pkh(v0.z, v0.w));
        ur[lane + 32] = make_uint2(pkh(v1.x, v1.y), pkh(v1.z, v1.w));
    }
    if (fcopy) {
        float4* fp = reinterpret_cast<float4*>(fcopy);
        fp[lane] = v0;
        fp[lane + 32] = v1;
    }
}

// ---------------- logits GEMM: cos = Ahat @ Bhat^T --------------------------
// Normalized fp16 operands + FP16 ACCUMULATE. BM=128, BN=128, BK=64, 256 thr,
// 8 warps 4(m)x2(n). blockIdx.z = which. Epilogue: cvt, exp, store;
// quad-reduced partial sumexp -> g_partial[row][bn*2+wn].
__global__ __launch_bounds__(256) void logits_kernel(
    float* __restrict__ out0, float* __restrict__ out1, int N, int S)
{
    extern __shared__ __align__(16) char sm[];
    __half* As = (__half*)sm;              // [2][128][72]
    __half* Bs = (__half*)(sm + 36864);    // [2][128][72]
    const int which = blockIdx.z;
    float* out = which ? out1 : out0;
    const __half* A = which ? g_fa_h : g_sp_h;
    const __half* B = which ? g_fkmn_h : g_svmn_h;
    const int naoff = which ? N : 0;
    const int tid = threadIdx.x;
    const int warp = tid >> 5, lane = tid & 31;
    const int wm = warp >> 1, wn = warp & 1;
    const long bm = blockIdx.y, bn = blockIdx.x;
    const __half* Ab = A + bm * 128 * 256;
    const __half* Bb = B + bn * 128 * 256;
    uint32_t sa = (uint32_t)__cvta_generic_to_shared(As);
    uint32_t sb = (uint32_t)__cvta_generic_to_shared(Bs);
    const int lr = tid >> 3, lc = (tid & 7) * 8;   // chunk: 8 halves

    unsigned acc[2][8][2] = {};   // f16x2 accumulators

    // prologue: stage 0
    #pragma unroll
    for (int i = 0; i < 4; i++) {
        int r = lr + i * 32;
        cpa16(sa + (unsigned)(r * 72 + lc) * 2, Ab + r * 256 + lc);
        cpa16(sb + (unsigned)(r * 72 + lc) * 2, Bb + r * 256 + lc);
    }
    CP_COMMIT;

    for (int kb = 0; kb < 4; ++kb) {
        if (kb < 3) {
            int st = (kb + 1) & 1;
            #pragma unroll
            for (int i = 0; i < 4; i++) {
                int r = lr + i * 32;
                cpa16(sa + (unsigned)(st * 9216 + r * 72 + lc) * 2, Ab + r * 256 + (kb + 1) * 64 + lc);
                cpa16(sb + (unsigned)(st * 9216 + r * 72 + lc) * 2, Bb + r * 256 + (kb + 1) * 64 + lc);
            }
        }
        CP_COMMIT;
        CP_WAIT(1);
        __syncthreads();
        const __half* Ast = As + (kb & 1) * 9216;
        const __half* Bst = Bs + (kb & 1) * 9216;
        #pragma unroll
        for (int kk = 0; kk < 4; ++kk) {
            unsigned a[2][4], b[4][4];
            #pragma unroll
            for (int mt = 0; mt < 2; ++mt) {
                int r = wm * 32 + mt * 16 + (lane & 15);
                int c = kk * 16 + ((lane >> 4) << 3);
                ldsm4(a[mt], Ast + r * 72 + c);
            }
            #pragma unroll
            for (int np = 0; np < 4; ++np) {
                int g = lane >> 3;
                int r = wn * 64 + np * 16 + ((g >> 1) << 3) + (lane & 7);
                int c = kk * 16 + ((g & 1) << 3);
                ldsm4(b[np], Bst + r * 72 + c);
            }
            #pragma unroll
            for (int mt = 0; mt < 2; ++mt)
                #pragma unroll
                for (int nt = 0; nt < 8; ++nt)
                    mma16816h(acc[mt][nt], a[mt], b[nt >> 1][(nt & 1) * 2], b[nt >> 1][(nt & 1) * 2 + 1]);
        }
        __syncthreads();
    }

    #pragma unroll
    for (int mt = 0; mt < 2; ++mt) {
        int r = (int)(bm * 128) + wm * 32 + mt * 16 + (lane >> 2);
        float ps0 = 0.f, ps1 = 0.f;
        #pragma unroll
        for (int nt = 0; nt < 8; ++nt) {
            int c = (int)(bn * 128) + wn * 64 + nt * 8 + (lane & 3) * 2;
            float2 f0 = __half22float2(*reinterpret_cast<__half2*>(&acc[mt][nt][0]));
            float2 f1 = __half22float2(*reinterpret_cast<__half2*>(&acc[mt][nt][1]));
            ps0 += __expf(f0.x) + __expf(f0.y);
            ps1 += __expf(f1.x) + __expf(f1.y);
            *reinterpret_cast<float2*>(out + (long)r * S + c) = make_float2(f0.x, f0.y);
            *reinterpret_cast<float2*>(out + (long)(r + 8) * S + c) = make_float2(f1.x, f1.y);
        }
        // quad reduction (lanes differing in bits 0,1 share the same rows)
        ps0 += __shfl_xor_sync(0xffffffffu, ps0, 1);
        ps0 += __shfl_xor_sync(0xffffffffu, ps0, 2);
        ps1 += __shfl_xor_sync(0xffffffffu, ps1, 1);
        ps1 += __shfl_xor_sync(0xffffffffu, ps1, 2);
        if ((lane & 3) == 0) {
            int chunk = (int)bn * 2 + wn;
            g_partial[(long)(naoff + r) * 64 + chunk] = ps0;
            g_partial[(long)(naoff + r + 8) * 64 + chunk] = ps1;
        }
    }
}

// ---------------- recall GEMM + address_log finalize ----------------------
// blockIdx.y selects speech/face (merged launch). Ls = log(sum of 64
// partials, fixed order). out_addr_log = logit - lse (written back);
// P' = exp(.+8) fp16; recall = exp(-8) * (P' @ svm). BM=64, BN=256, BK=64.
__global__ __launch_bounds__(256) void recall_kernel(
    float* __restrict__ logits0, float* __restrict__ logits1,
    float* __restrict__ outR0, float* __restrict__ outR1, int N, int S)
{
    extern __shared__ __align__(16) char sm[];
    __half* Vs = (__half*)sm;                        // [2][64][264]
    float*  Lf = (float*)(sm + 67584);               // [2][64][68]
    __half* Ps = (__half*)(sm + 67584 + 34816);      // [2][64][72]
    float*  Ls = (float*)(sm + 67584 + 34816 + 18432);
    const __half* V = g_svm_h;   // both recalls use raw speech_value_memory
    const int which = blockIdx.y;
    float* logits = which ? logits1 : logits0;
    float* outR   = which ? outR1   : outR0;
    const int lseoff = which ? N : 0;
    const int tid = threadIdx.x;
    const int warp = tid >> 5, lane = tid & 31;
    const int wm = warp >> 2, wn = warp & 3;
    const long bm = blockIdx.x;
    float* Lg = logits + bm * 64 * (long)S;
    uint32_t sv = (uint32_t)__cvta_generic_to_shared(Vs);
    uint32_t sl = (uint32_t)__cvta_generic_to_shared(Lf);

    if (tid < 64) {
        const float4* pp = reinterpret_cast<const float4*>(g_partial + (long)(lseoff + bm * 64 + tid) * 64);
        float s = 0.f;
        #pragma unroll
        for (int j = 0; j < 16; j++) { float4 v = pp[j]; s += v.x + v.y + v.z + v.w; }
        Ls[tid] = logf(s);
    }

    float acc[2][8][4] = {};

    // prologue loads stage 0
    #pragma unroll
    for (int i = 0; i < 8; i++) {
        int idx = tid + i * 256, r = idx >> 5, c = idx & 31;
        cpa16(sv + (unsigned)(r * 264 + c * 8) * 2, V + (long)r * 256 + c * 8);
    }
    #pragma unroll
    for (int i = 0; i < 4; i++) {
        int idx = tid + i * 256, r = idx >> 4, c = idx & 15;
        cpa16(sl + (unsigned)(r * 68 + c * 4) * 4, Lg + (long)r * S + c * 4);
    }
    CP_COMMIT;

    const int KB = S / 64;
    for (int kb = 0; kb < KB; ++kb) {
        CP_WAIT(0);
        __syncthreads();
        if (kb < KB - 1) {
            int st = (kb + 1) & 1;
            #pragma unroll
            for (int i = 0; i < 8; i++) {
                int idx = tid + i * 256, r = idx >> 5, c = idx & 31;
                cpa16(sv + (unsigned)(st * 16896 + r * 264 + c * 8) * 2,
                      V + (long)((kb + 1) * 64 + r) * 256 + c * 8);
            }
            #pragma unroll
            for (int i = 0; i < 4; i++) {
                int idx = tid + i * 256, r = idx >> 4, c = idx & 15;
                cpa16(sl + (unsigned)(st * 4352 + r * 68 + c * 4) * 4,
                      Lg + (long)r * S + (kb + 1) * 64 + c * 4);
            }
            CP_COMMIT;
        }
        const int st = kb & 1;
        // build Ps from Lf + writeback address_log
        #pragma unroll
        for (int i = 0; i < 4; i++) {
            int idx = tid + i * 256, r = idx >> 4, c = idx & 15;
            float4 v = *reinterpret_cast<float4*>(Lf + st * 4352 + r * 68 + c * 4);
            float l = Ls[r];
            v.x -= l; v.y -= l; v.z -= l; v.w -= l;
            *reinterpret_cast<float4*>(Lg + (long)r * S + kb * 64 + c * 4) = v;
            *reinterpret_cast<uint2*>(Ps + st * 4608 + r * 72 + c * 4) =
                make_uint2(pkh(__expf(v.x + PSHIFT), __expf(v.y + PSHIFT)),
                           pkh(__expf(v.z + PSHIFT), __expf(v.w + PSHIFT)));
        }
        __syncthreads();
        const __half* Pst = Ps + st * 4608;
        const __half* Vst = Vs + st * 16896;
        #pragma unroll
        for (int kk = 0; kk < 4; ++kk) {
            unsigned a[2][4], b[4][4];
            #pragma unroll
            for (int mt = 0; mt < 2; ++mt) {
                int r = wm * 32 + mt * 16 + (lane & 15);
                int c = kk * 16 + ((lane >> 4) << 3);
                ldsm4(a[mt], Pst + r * 72 + c);
            }
            #pragma unroll
            for (int np = 0; np < 4; ++np) {   // V rows=k, cols=n -> trans
                int g = lane >> 3;
                int r = kk * 16 + ((g & 1) << 3) + (lane & 7);
                int c = wn * 64 + np * 16 + ((g >> 1) << 3);
                ldsm4t(b[np], Vst + r * 264 + c);
            }
            #pragma unroll
            for (int mt = 0; mt < 2; ++mt)
                #pragma unroll
                for (int nt = 0; nt < 8; ++nt)
                    mma16816(acc[mt][nt], a[mt], b[nt >> 1][(nt & 1) * 2], b[nt >> 1][(nt & 1) * 2 + 1]);
        }
        __syncthreads();
    }

    #pragma unroll
    for (int mt = 0; mt < 2; ++mt) {
        int r = (int)(bm * 64) + wm * 32 + mt * 16 + (lane >> 2);
        #pragma unroll
        for (int nt = 0; nt < 8; ++nt) {
            int c = wn * 64 + nt * 8 + (lane & 3) * 2;
            *reinterpret_cast<float2*>(outR + (long)r * 256 + c) =
                make_float2(acc[mt][nt][0] * PSCALE, acc[mt][nt][1] * PSCALE);
            *reinterpret_cast<float2*>(outR + (long)(r + 8) * 256 + c) =
                make_float2(acc[mt][nt][2] * PSCALE, acc[mt][nt][3] * PSCALE);
        }
    }
}

// ---------------------------------------------------------------------------
static const int LOG_SMEM = 73728;
static const int REC_SMEM = 67584 + 34816 + 18432 + 256;

extern "C" void kernel_launch(void* const* d_in, const int* in_sizes, int n_in,
                              void* d_out, int out_size) {
    const float* face   = (const float*)d_in[0];
    const float* speech = (const float*)d_in[1];
    const float* svm    = (const float*)d_in[2];
    const float* fkm    = (const float*)d_in[3];
    const int C = 256;
    const int N = in_sizes[0] / C;   // 8192
    const int S = in_sizes[2] / C;   // 4096
    float* out = (float*)d_out;
    const long NC = (long)N * C;
    const long NS = (long)N * S;

    float* o_semb = out;               // speech_emb
    float* o_srec = out + NC;          // speech_emb_recall
    float* o_femb = out + 2 * NC;      // face_emb
    float* o_frec = out + 3 * NC;      // face_emb_recall
    float* o_slog = out + 4 * NC;      // speech_address_log (holds raw cos first)
    float* o_flog = out + 4 * NC + NS; // face_address_log

    cudaFuncSetAttribute(logits_kernel, cudaFuncAttributeMaxDynamicSharedMemorySize, LOG_SMEM);
    cudaFuncSetAttribute(recall_kernel, cudaFuncAttributeMaxDynamicSharedMemorySize, REC_SMEM);

    int rows = 2 * N + 2 * S;
    convert_norms_kernel<<<(rows + 7) / 8, 256>>>(face, speech, svm, fkm, o_semb, o_femb, N, S);

    dim3 g2(S / 128, N / 128, 2);
    logits_kernel<<<g2, 256, LOG_SMEM>>>(o_slog, o_flog, N, S);

    dim3 g3(N / 64, 2);
    recall_kernel<<<g3, 256, REC_SMEM>>>(o_slog, o_flog, o_srec, o_frec, N, S);
}

// round 15
// speedup vs baseline: 1.3633x; 1.0813x over previous
#include <cuda_runtime.h>
#include <cuda_fp16.h>
#include <cstdint>

#define PSHIFT 8.0f
#define PSCALE 0.000335462627902512f   // exp(-8)
#define E8F    2980.9580f              // exp(+8)

// scratch (N<=8192, S<=4096 for this problem)
static __device__ float g_partial[16384 * 64]; // per-row partial sumexp (64 chunks/row)
static __device__ __half g_P[16384 * 4096];    // P' = exp(cos+8) fp16; speech [0,N), face [N,2N)
static __device__ __half g_sp_h[8192 * 256];   // normalized speech
static __device__ __half g_fa_h[8192 * 256];   // normalized face
static __device__ __half g_svmn_h[4096 * 256]; // normalized svm (logits B)
static __device__ __half g_fkmn_h[4096 * 256]; // normalized fkm (logits B)
static __device__ __half g_svm_h[4096 * 256];  // RAW svm (recall V)

__device__ __forceinline__ unsigned pkh(float a, float b){
    __half2 h = __floats2half2_rn(a, b);
    return *reinterpret_cast<unsigned*>(&h);
}
__device__ __forceinline__ void cpa16(uint32_t dst, const void* src){
    asm volatile("cp.async.cg.shared.global [%0], [%1], 16;\n" :: "r"(dst), "l"(src));
}
#define CP_COMMIT asm volatile("cp.async.commit_group;\n" ::: "memory")
#define CP_WAIT(n) asm volatile("cp.async.wait_group %0;\n" :: "n"(n) : "memory")

__device__ __forceinline__ void ldsm4(unsigned r[4], const void* p){
    uint32_t a = (uint32_t)__cvta_generic_to_shared(p);
    asm volatile("ldmatrix.sync.aligned.m8n8.x4.shared.b16 {%0,%1,%2,%3}, [%4];\n"
        : "=r"(r[0]), "=r"(r[1]), "=r"(r[2]), "=r"(r[3]) : "r"(a));
}
__device__ __forceinline__ void ldsm4t(unsigned r[4], const void* p){
    uint32_t a = (uint32_t)__cvta_generic_to_shared(p);
    asm volatile("ldmatrix.sync.aligned.m8n8.x4.trans.shared.b16 {%0,%1,%2,%3}, [%4];\n"
        : "=r"(r[0]), "=r"(r[1]), "=r"(r[2]), "=r"(r[3]) : "r"(a));
}
// f32 accumulate (recall)
__device__ __forceinline__ void mma16816(float c[4], const unsigned a[4], unsigned b0, unsigned b1){
    asm volatile("mma.sync.aligned.m16n8k16.row.col.f32.f16.f16.f32 "
        "{%0,%1,%2,%3}, {%4,%5,%6,%7}, {%8,%9}, {%0,%1,%2,%3};\n"
        : "+f"(c[0]), "+f"(c[1]), "+f"(c[2]), "+f"(c[3])
        : "r"(a[0]), "r"(a[1]), "r"(a[2]), "r"(a[3]), "r"(b0), "r"(b1));
}
// f16 accumulate (logits)
__device__ __forceinline__ void mma16816h(unsigned c[2], const unsigned a[4], unsigned b0, unsigned b1){
    asm volatile("mma.sync.aligned.m16n8k16.row.col.f16.f16.f16.f16 "
        "{%0,%1}, {%2,%3,%4,%5}, {%6,%7}, {%0,%1};\n"
        : "+r"(c[0]), "+r"(c[1])
        : "r"(a[0]), "r"(a[1]), "r"(a[2]), "r"(a[3]), "r"(b0), "r"(b1));
}

// ------- fused convert + normalize + identity-embedding copy ---------------
__global__ void convert_norms_kernel(const float* __restrict__ face, const float* __restrict__ speech,
                                     const float* __restrict__ svm, const float* __restrict__ fkm,
                                     float* __restrict__ out_se, float* __restrict__ out_fe,
                                     int N, int S){
    int warp = threadIdx.x >> 5, lane = threadIdx.x & 31;
    int rid = blockIdx.x * 8 + warp;
    int total = 2*N + 2*S;
    if (rid >= total) return;
    const float* src; __half* hdst; __half* hraw = nullptr; float* fcopy = nullptr;
    if (rid < N)            { src = speech + (long)rid * 256; hdst = g_sp_h + (long)rid * 256;
                              fcopy = out_se + (long)rid * 256; }
    else if (rid < 2*N)     { int r = rid - N; src = face + (long)r * 256; hdst = g_fa_h + (long)r * 256;
                              fcopy = out_fe + (long)r * 256; }
    else if (rid < 2*N + S) { int r = rid - 2*N; src = svm + (long)r * 256;
                              hdst = g_svmn_h + (long)r * 256; hraw = g_svm_h + (long)r * 256; }
    else                    { int r = rid - 2*N - S; src = fkm + (long)r * 256; hdst = g_fkmn_h + (long)r * 256; }
    const float4* p = reinterpret_cast<const float4*>(src);
    float4 v0 = p[lane], v1 = p[lane + 32];
    float s = v0.x*v0.x + v0.y*v0.y + v0.z*v0.z + v0.w*v0.w
            + v1.x*v1.x + v1.y*v1.y + v1.z*v1.z + v1.w*v1.w;
    #pragma unroll
    for (int o = 16; o; o >>= 1) s += __shfl_xor_sync(0xffffffffu, s, o);
    float inv = rsqrtf(s);
    uint2* up = reinterpret_cast<uint2*>(hdst);
    up[lane]      = make_uint2(pkh(v0.x*inv, v0.y*inv), pkh(v0.z*inv, v0.w*inv));
    up[lane + 32] = make_uint2(pkh(v1.x*inv, v1.y*inv), pkh(v1.z*inv, v1.w*inv));
    if (hraw) {
        uint2* ur = reinterpret_cast<uint2*>(hraw);
        ur[lane]      = make_uint2(pkh(v0.x, v0.y), pkh(v0.z, v0.w));
        ur[lane + 32] = make_uint2(pkh(v1.x, v1.y), pkh(v1.z, v1.w));
    }
    if (fcopy) {
        float4* fp = reinterpret_cast<float4*>(fcopy);
        fp[lane] = v0;
        fp[lane + 32] = v1;
    }
}

// ---------------- logits GEMM: cos = Ahat @ Bhat^T --------------------------
// Normalized fp16 operands + FP16 ACCUMULATE. BM=128, BN=128, BK=64, 256 thr,
// 8 warps 4(m)x2(n). blockIdx.z = which.
// Epilogue: P' = exp(cos+8) fp16 -> g_P (NO f32 cos buffer at all);
// quad-reduced partial sumexp -> g_partial[row][bn*2+wn].
__global__ __launch_bounds__(256) void logits_kernel(int N, int S)
{
    extern __shared__ __align__(16) char sm[];
    __half* As = (__half*)sm;              // [2][128][72]
    __half* Bs = (__half*)(sm + 36864);    // [2][128][72]
    const int which = blockIdx.z;
    const __half* A = which ? g_fa_h : g_sp_h;
    const __half* B = which ? g_fkmn_h : g_svmn_h;
    const int naoff = which ? N : 0;
    const int tid = threadIdx.x;
    const int warp = tid >> 5, lane = tid & 31;
    const int wm = warp >> 1, wn = warp & 1;
    const long bm = blockIdx.y, bn = blockIdx.x;
    const __half* Ab = A + bm * 128 * 256;
    const __half* Bb = B + bn * 128 * 256;
    uint32_t sa = (uint32_t)__cvta_generic_to_shared(As);
    uint32_t sb = (uint32_t)__cvta_generic_to_shared(Bs);
    const int lr = tid >> 3, lc = (tid & 7) * 8;   // chunk: 8 halves

    unsigned acc[2][8][2] = {};   // f16x2 accumulators

    // prologue: stage 0
    #pragma unroll
    for (int i = 0; i < 4; i++) {
        int r = lr + i * 32;
        cpa16(sa + (unsigned)(r * 72 + lc) * 2, Ab + r * 256 + lc);
        cpa16(sb + (unsigned)(r * 72 + lc) * 2, Bb + r * 256 + lc);
    }
    CP_COMMIT;

    for (int kb = 0; kb < 4; ++kb) {
        if (kb < 3) {
            int st = (kb + 1) & 1;
            #pragma unroll
            for (int i = 0; i < 4; i++) {
                int r = lr + i * 32;
                cpa16(sa + (unsigned)(st * 9216 + r * 72 + lc) * 2, Ab + r * 256 + (kb + 1) * 64 + lc);
                cpa16(sb + (unsigned)(st * 9216 + r * 72 + lc) * 2, Bb + r * 256 + (kb + 1) * 64 + lc);
            }
        }
        CP_COMMIT;
        CP_WAIT(1);
        __syncthreads();
        const __half* Ast = As + (kb & 1) * 9216;
        const __half* Bst = Bs + (kb & 1) * 9216;
        #pragma unroll
        for (int kk = 0; kk < 4; ++kk) {
            unsigned a[2][4], b[4][4];
            #pragma unroll
            for (int mt = 0; mt < 2; ++mt) {
                int r = wm * 32 + mt * 16 + (lane & 15);
                int c = kk * 16 + ((lane >> 4) << 3);
                ldsm4(a[mt], Ast + r * 72 + c);
            }
            #pragma unroll
            for (int np = 0; np < 4; ++np) {
                int g = lane >> 3;
                int r = wn * 64 + np * 16 + ((g >> 1) << 3) + (lane & 7);
                int c = kk * 16 + ((g & 1) << 3);
                ldsm4(b[np], Bst + r * 72 + c);
            }
            #pragma unroll
            for (int mt = 0; mt < 2; ++mt)
                #pragma unroll
                for (int nt = 0; nt < 8; ++nt)
                    mma16816h(acc[mt][nt], a[mt], b[nt >> 1][(nt & 1) * 2], b[nt >> 1][(nt & 1) * 2 + 1]);
        }
        __syncthreads();
    }

    #pragma unroll
    for (int mt = 0; mt < 2; ++mt) {
        int r = (int)(bm * 128) + wm * 32 + mt * 16 + (lane >> 2);
        float ps0 = 0.f, ps1 = 0.f;
        #pragma unroll
        for (int nt = 0; nt < 8; ++nt) {
            int c = (int)(bn * 128) + wn * 64 + nt * 8 + (lane & 3) * 2;
            float2 f0 = __half22float2(*reinterpret_cast<__half2*>(&acc[mt][nt][0]));
            float2 f1 = __half22float2(*reinterpret_cast<__half2*>(&acc[mt][nt][1]));
            float e00 = __expf(f0.x), e01 = __expf(f0.y);
            float e10 = __expf(f1.x), e11 = __expf(f1.y);
            ps0 += e00 + e01;
            ps1 += e10 + e11;
            *reinterpret_cast<unsigned*>(&g_P[(long)(naoff + r) * S + c]) = pkh(e00 * E8F, e01 * E8F);
            *reinterpret_cast<unsigned*>(&g_P[(long)(naoff + r + 8) * S + c]) = pkh(e10 * E8F, e11 * E8F);
        }
        // quad reduction (lanes differing in bits 0,1 share the same rows)
        ps0 += __shfl_xor_sync(0xffffffffu, ps0, 1);
        ps0 += __shfl_xor_sync(0xffffffffu, ps0, 2);
        ps1 += __shfl_xor_sync(0xffffffffu, ps1, 1);
        ps1 += __shfl_xor_sync(0xffffffffu, ps1, 2);
        if ((lane & 3) == 0) {
            int chunk = (int)bn * 2 + wn;
            g_partial[(long)(naoff + r) * 64 + chunk] = ps0;
            g_partial[(long)(naoff + r + 8) * 64 + chunk] = ps1;
        }
    }
}

// ---------------- recall GEMM (pure fp16 operands) + addr_log --------------
// P' and V tiles via cp.async (2 stages, ONE barrier/iter). addr_log =
// ln(P') - 8 - ln(s) computed from the P' smem tile (MUFU.LG2, off the mma
// feed path). recall = (exp(-8)/sumexp) * (P' @ V). BM=64, BN=256, BK=64,
// 256 thr, warps 2(m)x4(n). blockIdx.y = which.
__global__ __launch_bounds__(256) void recall_kernel(
    float* __restrict__ logits0, float* __restrict__ logits1,
    float* __restrict__ outR0, float* __restrict__ outR1, int N, int S)
{
    extern __shared__ __align__(16) char sm[];
    __half* Vs = (__half*)sm;                  // [2][64][264]
    __half* Ps = (__half*)(sm + 67584);        // [2][64][72]
    float*  Lsp = (float*)(sm + 86016);        // 64: PSHIFT + ln(sumexp)
    float*  Si  = (float*)(sm + 86272);        // 64: exp(-8)/sumexp
    const __half* V = g_svm_h;   // both recalls use raw speech_value_memory
    const int which = blockIdx.y;
    float* logits = which ? logits1 : logits0;
    float* outR   = which ? outR1   : outR0;
    const int lseoff = which ? N : 0;
    const int tid = threadIdx.x;
    const int warp = tid >> 5, lane = tid & 31;
    const int wm = warp >> 2, wn = warp & 3;
    const long bm = blockIdx.x;
    float* Lg = logits + bm * 64 * (long)S;
    const __half* Pg = g_P + (long)(lseoff + bm * 64) * S;
    uint32_t sv = (uint32_t)__cvta_generic_to_shared(Vs);
    uint32_t sp = (uint32_t)__cvta_generic_to_shared(Ps);

    if (tid < 64) {
        const float4* pp = reinterpret_cast<const float4*>(g_partial + (long)(lseoff + bm * 64 + tid) * 64);
        float s = 0.f;
        #pragma unroll
        for (int j = 0; j < 16; j++) { float4 v = pp[j]; s += v.x + v.y + v.z + v.w; }
        Lsp[tid] = PSHIFT + logf(s);
        Si[tid]  = PSCALE / s;
    }

    float acc[2][8][4] = {};

    // prologue: stage 0
    #pragma unroll
    for (int i = 0; i < 8; i++) {
        int idx = tid + i * 256, r = idx >> 5, c = idx & 31;
        cpa16(sv + (unsigned)(r * 264 + c * 8) * 2, V + (long)r * 256 + c * 8);
    }
    #pragma unroll
    for (int i = 0; i < 2; i++) {
        int idx = tid + i * 256, r = idx >> 3, c8 = (idx & 7) * 8;
        cpa16(sp + (unsigned)(r * 72 + c8) * 2, Pg + (long)r * S + c8);
    }
    CP_COMMIT;

    const int KB = S / 64;
    for (int kb = 0; kb < KB; ++kb) {
        CP_WAIT(0);
        __syncthreads();
        if (kb < KB - 1) {
            int st = (kb + 1) & 1;
            #pragma unroll
            for (int i = 0; i < 8; i++) {
                int idx = tid + i * 256, r = idx >> 5, c = idx & 31;
                cpa16(sv + (unsigned)(st * 16896 + r * 264 + c * 8) * 2,
                      V + (long)((kb + 1) * 64 + r) * 256 + c * 8);
            }
            #pragma unroll
            for (int i = 0; i < 2; i++) {
                int idx = tid + i * 256, r = idx >> 3, c8 = (idx & 7) * 8;
                cpa16(sp + (unsigned)(st * 4608 + r * 72 + c8) * 2,
                      Pg + (long)r * S + (kb + 1) * 64 + c8);
            }
            CP_COMMIT;
        }
        const int st = kb & 1;
        // addr_log from the P' tile: ln(P') - (8 + ln(s))
        #pragma unroll
        for (int i = 0; i < 2; i++) {
            int idx = tid + i * 256, r = idx >> 3, c8 = (idx & 7) * 8;
            const __half2* ph = reinterpret_cast<const __half2*>(Ps + st * 4608 + r * 72 + c8);
            float lsp = Lsp[r];
            float2 a0 = __half22float2(ph[0]);
            float2 a1 = __half22float2(ph[1]);
            float2 a2 = __half22float2(ph[2]);
            float2 a3 = __half22float2(ph[3]);
            float4 o0, o1;
            o0.x = __logf(a0.x) - lsp; o0.y = __logf(a0.y) - lsp;
            o0.z = __logf(a1.x) - lsp; o0.w = __logf(a1.y) - lsp;
            o1.x = __logf(a2.x) - lsp; o1.y = __logf(a2.y) - lsp;
            o1.z = __logf(a3.x) - lsp; o1.w = __logf(a3.y) - lsp;
            float* op = Lg + (long)r * S + kb * 64 + c8;
            *reinterpret_cast<float4*>(op) = o0;
            *reinterpret_cast<float4*>(op + 4) = o1;
        }
        const __half* Pst = Ps + st * 4608;
        const __half* Vst = Vs + st * 16896;
        #pragma unroll
        for (int kk = 0; kk < 4; ++kk) {
            unsigned a[2][4], b[4][4];
            #pragma unroll
            for (int mt = 0; mt < 2; ++mt) {
                int r = wm * 32 + mt * 16 + (lane & 15);
                int c = kk * 16 + ((lane >> 4) << 3);
                ldsm4(a[mt], Pst + r * 72 + c);
            }
            #pragma unroll
            for (int np = 0; np < 4; ++np) {   // V rows=k, cols=n -> trans
                int g = lane >> 3;
                int r = kk * 16 + ((g & 1) << 3) + (lane & 7);
                int c = wn * 64 + np * 16 + ((g >> 1) << 3);
                ldsm4t(b[np], Vst + r * 264 + c);
            }
            #pragma unroll
            for (int mt = 0; mt < 2; ++mt)
                #pragma unroll
                for (int nt = 0; nt < 8; ++nt)
                    mma16816(acc[mt][nt], a[mt], b[nt >> 1][(nt & 1) * 2], b[nt >> 1][(nt & 1) * 2 + 1]);
        }
    }

    #pragma unroll
    for (int mt = 0; mt < 2; ++mt) {
        int rl = wm * 32 + mt * 16 + (lane >> 2);
        int r = (int)(bm * 64) + rl;
        float s0 = Si[rl], s1 = Si[rl + 8];
        #pragma unroll
        for (int nt = 0; nt < 8; ++nt) {
            int c = wn * 64 + nt * 8 + (lane & 3) * 2;
            *reinterpret_cast<float2*>(outR + (long)r * 256 + c) =
                make_float2(acc[mt][nt][0] * s0, acc[mt][nt][1] * s0);
            *reinterpret_cast<float2*>(outR + (long)(r + 8) * 256 + c) =
                make_float2(acc[mt][nt][2] * s1, acc[mt][nt][3] * s1);
        }
    }
}

// ---------------------------------------------------------------------------
static const int LOG_SMEM = 73728;
static const int REC_SMEM = 86528;

extern "C" void kernel_launch(void* const* d_in, const int* in_sizes, int n_in,
                              void* d_out, int out_size) {
    const float* face   = (const float*)d_in[0];
    const float* speech = (const float*)d_in[1];
    const float* svm    = (const float*)d_in[2];
    const float* fkm    = (const float*)d_in[3];
    const int C = 256;
    const int N = in_sizes[0] / C;   // 8192
    const int S = in_sizes[2] / C;   // 4096
    float* out = (float*)d_out;
    const long NC = (long)N * C;
    const long NS = (long)N * S;

    float* o_semb = out;               // speech_emb
    float* o_srec = out + NC;          // speech_emb_recall
    float* o_femb = out + 2 * NC;      // face_emb
    float* o_frec = out + 3 * NC;      // face_emb_recall
    float* o_slog = out + 4 * NC;      // speech_address_log
    float* o_flog = out + 4 * NC + NS; // face_address_log

    cudaFuncSetAttribute(logits_kernel, cudaFuncAttributeMaxDynamicSharedMemorySize, LOG_SMEM);
    cudaFuncSetAttribute(recall_kernel, cudaFuncAttributeMaxDynamicSharedMemorySize, REC_SMEM);

    int rows = 2 * N + 2 * S;
    convert_norms_kernel<<<(rows + 7) / 8, 256>>>(face, speech, svm, fkm, o_semb, o_femb, N, S);

    dim3 g2(S / 128, N / 128, 2);
    logits_kernel<<<g2, 256, LOG_SMEM>>>(N, S);

    dim3 g3(N / 64, 2);
    recall_kernel<<<g3, 256, REC_SMEM>>>(o_slog, o_flog, o_srec, o_frec, N, S);
}

// round 16
// speedup vs baseline: 1.4288x; 1.0480x over previous
#include <cuda_runtime.h>
#include <cuda_fp16.h>
#include <cstdint>

#define PSHIFT 8.0f
#define PSCALE 0.000335462627902512f   // exp(-8)
#define E8F    2980.9580f              // exp(+8)

// scratch (N<=8192, S<=4096 for this problem)
static __device__ float g_partial[16384 * 64]; // per-row partial sumexp (64 chunks/row)
static __device__ __half g_P[16384 * 4096];    // P' = exp(cos+8) fp16; speech [0,N), face [N,2N)
static __device__ __half g_sp_h[8192 * 256];   // normalized speech
static __device__ __half g_fa_h[8192 * 256];   // normalized face
static __device__ __half g_svmn_h[4096 * 256]; // normalized svm (logits B)
static __device__ __half g_fkmn_h[4096 * 256]; // normalized fkm (logits B)
static __device__ __half g_svm_h[4096 * 256];  // RAW svm (recall V)

__device__ __forceinline__ unsigned pkh(float a, float b){
    __half2 h = __floats2half2_rn(a, b);
    return *reinterpret_cast<unsigned*>(&h);
}
__device__ __forceinline__ void cpa16(uint32_t dst, const void* src){
    asm volatile("cp.async.cg.shared.global [%0], [%1], 16;\n" :: "r"(dst), "l"(src));
}
#define CP_COMMIT asm volatile("cp.async.commit_group;\n" ::: "memory")
#define CP_WAIT(n) asm volatile("cp.async.wait_group %0;\n" :: "n"(n) : "memory")

__device__ __forceinline__ void ldsm4(unsigned r[4], const void* p){
    uint32_t a = (uint32_t)__cvta_generic_to_shared(p);
    asm volatile("ldmatrix.sync.aligned.m8n8.x4.shared.b16 {%0,%1,%2,%3}, [%4];\n"
        : "=r"(r[0]), "=r"(r[1]), "=r"(r[2]), "=r"(r[3]) : "r"(a));
}
__device__ __forceinline__ void ldsm4t(unsigned r[4], const void* p){
    uint32_t a = (uint32_t)__cvta_generic_to_shared(p);
    asm volatile("ldmatrix.sync.aligned.m8n8.x4.trans.shared.b16 {%0,%1,%2,%3}, [%4];\n"
        : "=r"(r[0]), "=r"(r[1]), "=r"(r[2]), "=r"(r[3]) : "r"(a));
}
// f32 accumulate (recall)
__device__ __forceinline__ void mma16816(float c[4], const unsigned a[4], unsigned b0, unsigned b1){
    asm volatile("mma.sync.aligned.m16n8k16.row.col.f32.f16.f16.f32 "
        "{%0,%1,%2,%3}, {%4,%5,%6,%7}, {%8,%9}, {%0,%1,%2,%3};\n"
        : "+f"(c[0]), "+f"(c[1]), "+f"(c[2]), "+f"(c[3])
        : "r"(a[0]), "r"(a[1]), "r"(a[2]), "r"(a[3]), "r"(b0), "r"(b1));
}
// f16 accumulate (logits)
__device__ __forceinline__ void mma16816h(unsigned c[2], const unsigned a[4], unsigned b0, unsigned b1){
    asm volatile("mma.sync.aligned.m16n8k16.row.col.f16.f16.f16.f16 "
        "{%0,%1}, {%2,%3,%4,%5}, {%6,%7}, {%0,%1};\n"
        : "+r"(c[0]), "+r"(c[1])
        : "r"(a[0]), "r"(a[1]), "r"(a[2]), "r"(a[3]), "r"(b0), "r"(b1));
}

// ------- fused convert + normalize + identity-embedding copy ---------------
__global__ void convert_norms_kernel(const float* __restrict__ face, const float* __restrict__ speech,
                                     const float* __restrict__ svm, const float* __restrict__ fkm,
                                     float* __restrict__ out_se, float* __restrict__ out_fe,
                                     int N, int S){
    int warp = threadIdx.x >> 5, lane = threadIdx.x & 31;
    int rid = blockIdx.x * 8 + warp;
    int total = 2*N + 2*S;
    if (rid >= total) return;
    const float* src; __half* hdst; __half* hraw = nullptr; float* fcopy = nullptr;
    if (rid < N)            { src = speech + (long)rid * 256; hdst = g_sp_h + (long)rid * 256;
                              fcopy = out_se + (long)rid * 256; }
    else if (rid < 2*N)     { int r = rid - N; src = face + (long)r * 256; hdst = g_fa_h + (long)r * 256;
                              fcopy = out_fe + (long)r * 256; }
    else if (rid < 2*N + S) { int r = rid - 2*N; src = svm + (long)r * 256;
                              hdst = g_svmn_h + (long)r * 256; hraw = g_svm_h + (long)r * 256; }
    else                    { int r = rid - 2*N - S; src = fkm + (long)r * 256; hdst = g_fkmn_h + (long)r * 256; }
    const float4* p = reinterpret_cast<const float4*>(src);
    float4 v0 = p[lane], v1 = p[lane + 32];
    float s = v0.x*v0.x + v0.y*v0.y + v0.z*v0.z + v0.w*v0.w
            + v1.x*v1.x + v1.y*v1.y + v1.z*v1.z + v1.w*v1.w;
    #pragma unroll
    for (int o = 16; o; o >>= 1) s += __shfl_xor_sync(0xffffffffu, s, o);
    float inv = rsqrtf(s);
    uint2* up = reinterpret_cast<uint2*>(hdst);
    up[lane]      = make_uint2(pkh(v0.x*inv, v0.y*inv), pkh(v0.z*inv, v0.w*inv));
    up[lane + 32] = make_uint2(pkh(v1.x*inv, v1.y*inv), pkh(v1.z*inv, v1.w*inv));
    if (hraw) {
        uint2* ur = reinterpret_cast<uint2*>(hraw);
        ur[lane]      = make_uint2(pkh(v0.x, v0.y), pkh(v0.z, v0.w));
        ur[lane + 32] = make_uint2(pkh(v1.x, v1.y), pkh(v1.z, v1.w));
    }
    if (fcopy) {
        float4* fp = reinterpret_cast<float4*>(fcopy);
        fp[lane] = v0;
        fp[lane + 32] = v1;
    }
}

// ---------------- logits GEMM: cos = Ahat @ Bhat^T --------------------------
// Normalized fp16 operands + FP16 ACCUMULATE. BM=128, BN=128, BK=64, 256 thr,
// 8 warps 4(m)x2(n). blockIdx.z = which. 2 CTAs/SM (prologue/epilogue overlap).
// Epilogue: P' = exp(cos+8) fp16 -> g_P; quad-reduced partial sumexp -> g_partial.
__global__ __launch_bounds__(256, 2) void logits_kernel(int N, int S)
{
    extern __shared__ __align__(16) char sm[];
    __half* As = (__half*)sm;              // [2][128][72]
    __half* Bs = (__half*)(sm + 36864);    // [2][128][72]
    const int which = blockIdx.z;
    const __half* A = which ? g_fa_h : g_sp_h;
    const __half* B = which ? g_fkmn_h : g_svmn_h;
    const int naoff = which ? N : 0;
    const int tid = threadIdx.x;
    const int warp = tid >> 5, lane = tid & 31;
    const int wm = warp >> 1, wn = warp & 1;
    const long bm = blockIdx.y, bn = blockIdx.x;
    const __half* Ab = A + bm * 128 * 256;
    const __half* Bb = B + bn * 128 * 256;
    uint32_t sa = (uint32_t)__cvta_generic_to_shared(As);
    uint32_t sb = (uint32_t)__cvta_generic_to_shared(Bs);
    const int lr = tid >> 3, lc = (tid & 7) * 8;   // chunk: 8 halves

    unsigned acc[2][8][2] = {};   // f16x2 accumulators

    // prologue: stage 0
    #pragma unroll
    for (int i = 0; i < 4; i++) {
        int r = lr + i * 32;
        cpa16(sa + (unsigned)(r * 72 + lc) * 2, Ab + r * 256 + lc);
        cpa16(sb + (unsigned)(r * 72 + lc) * 2, Bb + r * 256 + lc);
    }
    CP_COMMIT;

    for (int kb = 0; kb < 4; ++kb) {
        if (kb < 3) {
            int st = (kb + 1) & 1;
            #pragma unroll
            for (int i = 0; i < 4; i++) {
                int r = lr + i * 32;
                cpa16(sa + (unsigned)(st * 9216 + r * 72 + lc) * 2, Ab + r * 256 + (kb + 1) * 64 + lc);
                cpa16(sb + (unsigned)(st * 9216 + r * 72 + lc) * 2, Bb + r * 256 + (kb + 1) * 64 + lc);
            }
        }
        CP_COMMIT;
        CP_WAIT(1);
        __syncthreads();
        const __half* Ast = As + (kb & 1) * 9216;
        const __half* Bst = Bs + (kb & 1) * 9216;
        #pragma unroll
        for (int kk = 0; kk < 4; ++kk) {
            unsigned a[2][4], b[4][4];
            #pragma unroll
            for (int mt = 0; mt < 2; ++mt) {
                int r = wm * 32 + mt * 16 + (lane & 15);
                int c = kk * 16 + ((lane >> 4) << 3);
                ldsm4(a[mt], Ast + r * 72 + c);
            }
            #pragma unroll
            for (int np = 0; np < 4; ++np) {
                int g = lane >> 3;
                int r = wn * 64 + np * 16 + ((g >> 1) << 3) + (lane & 7);
                int c = kk * 16 + ((g & 1) << 3);
                ldsm4(b[np], Bst + r * 72 + c);
            }
            #pragma unroll
            for (int mt = 0; mt < 2; ++mt)
                #pragma unroll
                for (int nt = 0; nt < 8; ++nt)
                    mma16816h(acc[mt][nt], a[mt], b[nt >> 1][(nt & 1) * 2], b[nt >> 1][(nt & 1) * 2 + 1]);
        }
        __syncthreads();
    }

    #pragma unroll
    for (int mt = 0; mt < 2; ++mt) {
        int r = (int)(bm * 128) + wm * 32 + mt * 16 + (lane >> 2);
        float ps0 = 0.f, ps1 = 0.f;
        #pragma unroll
        for (int nt = 0; nt < 8; ++nt) {
            int c = (int)(bn * 128) + wn * 64 + nt * 8 + (lane & 3) * 2;
            float2 f0 = __half22float2(*reinterpret_cast<__half2*>(&acc[mt][nt][0]));
            float2 f1 = __half22float2(*reinterpret_cast<__half2*>(&acc[mt][nt][1]));
            float e00 = __expf(f0.x), e01 = __expf(f0.y);
            float e10 = __expf(f1.x), e11 = __expf(f1.y);
            ps0 += e00 + e01;
            ps1 += e10 + e11;
            *reinterpret_cast<unsigned*>(&g_P[(long)(naoff + r) * S + c]) = pkh(e00 * E8F, e01 * E8F);
            *reinterpret_cast<unsigned*>(&g_P[(long)(naoff + r + 8) * S + c]) = pkh(e10 * E8F, e11 * E8F);
        }
        // quad reduction (lanes differing in bits 0,1 share the same rows)
        ps0 += __shfl_xor_sync(0xffffffffu, ps0, 1);
        ps0 += __shfl_xor_sync(0xffffffffu, ps0, 2);
        ps1 += __shfl_xor_sync(0xffffffffu, ps1, 1);
        ps1 += __shfl_xor_sync(0xffffffffu, ps1, 2);
        if ((lane & 3) == 0) {
            int chunk = (int)bn * 2 + wn;
            g_partial[(long)(naoff + r) * 64 + chunk] = ps0;
            g_partial[(long)(naoff + r + 8) * 64 + chunk] = ps1;
        }
    }
}

// ---------------- recall GEMM (pure fp16 operands) + addr_log --------------
// P' and V tiles via cp.async (2 stages, ONE barrier/iter). 2 CTAs/SM.
// addr_log = ln(P') - 8 - ln(s) from the P' smem tile (off the mma feed path).
// recall = (exp(-8)/sumexp) * (P' @ V). BM=64, BN=256, BK=64, warps 2x4.
__global__ __launch_bounds__(256, 2) void recall_kernel(
    float* __restrict__ logits0, float* __restrict__ logits1,
    float* __restrict__ outR0, float* __restrict__ outR1, int N, int S)
{
    extern __shared__ __align__(16) char sm[];
    __half* Vs = (__half*)sm;                  // [2][64][264]
    __half* Ps = (__half*)(sm + 67584);        // [2][64][72]
    float*  Lsp = (float*)(sm + 86016);        // 64: PSHIFT + ln(sumexp)
    float*  Si  = (float*)(sm + 86272);        // 64: exp(-8)/sumexp
    const __half* V = g_svm_h;   // both recalls use raw speech_value_memory
    const int which = blockIdx.y;
    float* logits = which ? logits1 : logits0;
    float* outR   = which ? outR1   : outR0;
    const int lseoff = which ? N : 0;
    const int tid = threadIdx.x;
    const int warp = tid >> 5, lane = tid & 31;
    const int wm = warp >> 2, wn = warp & 3;
    const long bm = blockIdx.x;
    float* Lg = logits + bm * 64 * (long)S;
    const __half* Pg = g_P + (long)(lseoff + bm * 64) * S;
    uint32_t sv = (uint32_t)__cvta_generic_to_shared(Vs);
    uint32_t sp = (uint32_t)__cvta_generic_to_shared(Ps);

    if (tid < 64) {
        const float4* pp = reinterpret_cast<const float4*>(g_partial + (long)(lseoff + bm * 64 + tid) * 64);
        float s = 0.f;
        #pragma unroll
        for (int j = 0; j < 16; j++) { float4 v = pp[j]; s += v.x + v.y + v.z + v.w; }
        Lsp[tid] = PSHIFT + logf(s);
        Si[tid]  = PSCALE / s;
    }

    float acc[2][8][4] = {};

    // prologue: stage 0
    #pragma unroll
    for (int i = 0; i < 8; i++) {
        int idx = tid + i * 256, r = idx >> 5, c = idx & 31;
        cpa16(sv + (unsigned)(r * 264 + c * 8) * 2, V + (long)r * 256 + c * 8);
    }
    #pragma unroll
    for (int i = 0; i < 2; i++) {
        int idx = tid + i * 256, r = idx >> 3, c8 = (idx & 7) * 8;
        cpa16(sp + (unsigned)(r * 72 + c8) * 2, Pg + (long)r * S + c8);
    }
    CP_COMMIT;

    const int KB = S / 64;
    for (int kb = 0; kb < KB; ++kb) {
        CP_WAIT(0);
        __syncthreads();
        if (kb < KB - 1) {
            int st = (kb + 1) & 1;
            #pragma unroll
            for (int i = 0; i < 8; i++) {
                int idx = tid + i * 256, r = idx >> 5, c = idx & 31;
                cpa16(sv + (unsigned)(st * 16896 + r * 264 + c * 8) * 2,
                      V + (long)((kb + 1) * 64 + r) * 256 + c * 8);
            }
            #pragma unroll
            for (int i = 0; i < 2; i++) {
                int idx = tid + i * 256, r = idx >> 3, c8 = (idx & 7) * 8;
                cpa16(sp + (unsigned)(st * 4608 + r * 72 + c8) * 2,
                      Pg + (long)r * S + (kb + 1) * 64 + c8);
            }
            CP_COMMIT;
        }
        const int st = kb & 1;
        // addr_log from the P' tile: ln(P') - (8 + ln(s))
        #pragma unroll
        for (int i = 0; i < 2; i++) {
            int idx = tid + i * 256, r = idx >> 3, c8 = (idx & 7) * 8;
            const __half2* ph = reinterpret_cast<const __half2*>(Ps + st * 4608 + r * 72 + c8);
            float lsp = Lsp[r];
            float2 a0 = __half22float2(ph[0]);
            float2 a1 = __half22float2(ph[1]);
            float2 a2 = __half22float2(ph[2]);
            float2 a3 = __half22float2(ph[3]);
            float4 o0, o1;
            o0.x = __logf(a0.x) - lsp; o0.y = __logf(a0.y) - lsp;
            o0.z = __logf(a1.x) - lsp; o0.w = __logf(a1.y) - lsp;
            o1.x = __logf(a2.x) - lsp; o1.y = __logf(a2.y) - lsp;
            o1.z = __logf(a3.x) - lsp; o1.w = __logf(a3.y) - lsp;
            float* op = Lg + (long)r * S + kb * 64 + c8;
            *reinterpret_cast<float4*>(op) = o0;
            *reinterpret_cast<float4*>(op + 4) = o1;
        }
        const __half* Pst = Ps + st * 4608;
        const __half* Vst = Vs + st * 16896;
        #pragma unroll
        for (int kk = 0; kk < 4; ++kk) {
            unsigned a[2][4], b[4][4];
            #pragma unroll
            for (int mt = 0; mt < 2; ++mt) {
                int r = wm * 32 + mt * 16 + (lane & 15);
                int c = kk * 16 + ((lane >> 4) << 3);
                ldsm4(a[mt], Pst + r * 72 + c);
            }
            #pragma unroll
            for (int np = 0; np < 4; ++np) {   // V rows=k, cols=n -> trans
                int g = lane >> 3;
                int r = kk * 16 + ((g & 1) << 3) + (lane & 7);
                int c = wn * 64 + np * 16 + ((g >> 1) << 3);
                ldsm4t(b[np], Vst + r * 264 + c);
            }
            #pragma unroll
            for (int mt = 0; mt < 2; ++mt)
                #pragma unroll
                for (int nt = 0; nt < 8; ++nt)
                    mma16816(acc[mt][nt], a[mt], b[nt >> 1][(nt & 1) * 2], b[nt >> 1][(nt & 1) * 2 + 1]);
        }
    }

    #pragma unroll
    for (int mt = 0; mt < 2; ++mt) {
        int rl = wm * 32 + mt * 16 + (lane >> 2);
        int r = (int)(bm * 64) + rl;
        float s0 = Si[rl], s1 = Si[rl + 8];
        #pragma unroll
        for (int nt = 0; nt < 8; ++nt) {
            int c = wn * 64 + nt * 8 + (lane & 3) * 2;
            *reinterpret_cast<float2*>(outR + (long)r * 256 + c) =
                make_float2(acc[mt][nt][0] * s0, acc[mt][nt][1] * s0);
            *reinterpret_cast<float2*>(outR + (long)(r + 8) * 256 + c) =
                make_float2(acc[mt][nt][2] * s1, acc[mt][nt][3] * s1);
        }
    }
}

// ---------------------------------------------------------------------------
static const int LOG_SMEM = 73728;
static const int REC_SMEM = 86528;

extern "C" void kernel_launch(void* const* d_in, const int* in_sizes, int n_in,
                              void* d_out, int out_size) {
    const float* face   = (const float*)d_in[0];
    const float* speech = (const float*)d_in[1];
    const float* svm    = (const float*)d_in[2];
    const float* fkm    = (const float*)d_in[3];
    const int C = 256;
    const int N = in_sizes[0] / C;   // 8192
    const int S = in_sizes[2] / C;   // 4096
    float* out = (float*)d_out;
    const long NC = (long)N * C;
    const long NS = (long)N * S;

    float* o_semb = out;               // speech_emb
    float* o_srec = out + NC;          // speech_emb_recall
    float* o_femb = out + 2 * NC;      // face_emb
    float* o_frec = out + 3 * NC;      // face_emb_recall
    float* o_slog = out + 4 * NC;      // speech_address_log
    float* o_flog = out + 4 * NC + NS; // face_address_log

    cudaFuncSetAttribute(logits_kernel, cudaFuncAttributeMaxDynamicSharedMemorySize, LOG_SMEM);
    cudaFuncSetAttribute(recall_kernel, cudaFuncAttributeMaxDynamicSharedMemorySize, REC_SMEM);

    int rows = 2 * N + 2 * S;
    convert_norms_kernel<<<(rows + 7) / 8, 256>>>(face, speech, svm, fkm, o_semb, o_femb, N, S);

    dim3 g2(S / 128, N / 128, 2);
    logits_kernel<<<g2, 256, LOG_SMEM>>>(N, S);

    dim3 g3(N / 64, 2);
    recall_kernel<<<g3, 256, REC_SMEM>>>(o_slog, o_flog, o_srec, o_frec, N, S);
}

// round 17
// speedup vs baseline: 1.4789x; 1.0351x over previous
#include <cuda_runtime.h>
#include <cuda_fp16.h>
#include <cstdint>

#define PSHIFT 8.0f
#define PSCALE 0.000335462627902512f   // exp(-8)
#define E8F    2980.9580f              // exp(+8)

// scratch (N<=8192, S<=4096 for this problem)
static __device__ float g_partial[16384 * 64]; // per-row partial sumexp (64 chunks/row)
static __device__ __half g_P[16384 * 4096];    // P' = exp(cos+8) fp16; speech [0,N), face [N,2N)
static __device__ __half g_sp_h[8192 * 256];   // normalized speech
static __device__ __half g_fa_h[8192 * 256];   // normalized face
static __device__ __half g_svmn_h[4096 * 256]; // normalized svm (logits B)
static __device__ __half g_fkmn_h[4096 * 256]; // normalized fkm (logits B)
static __device__ __half g_svm_h[4096 * 256];  // RAW svm (recall V)

__device__ __forceinline__ unsigned pkh(float a, float b){
    __half2 h = __floats2half2_rn(a, b);
    return *reinterpret_cast<unsigned*>(&h);
}
__device__ __forceinline__ void cpa16(uint32_t dst, const void* src){
    asm volatile("cp.async.cg.shared.global [%0], [%1], 16;\n" :: "r"(dst), "l"(src));
}
#define CP_COMMIT asm volatile("cp.async.commit_group;\n" ::: "memory")
#define CP_WAIT(n) asm volatile("cp.async.wait_group %0;\n" :: "n"(n) : "memory")

__device__ __forceinline__ void ldsm4(unsigned r[4], const void* p){
    uint32_t a = (uint32_t)__cvta_generic_to_shared(p);
    asm volatile("ldmatrix.sync.aligned.m8n8.x4.shared.b16 {%0,%1,%2,%3}, [%4];\n"
        : "=r"(r[0]), "=r"(r[1]), "=r"(r[2]), "=r"(r[3]) : "r"(a));
}
__device__ __forceinline__ void ldsm4t(unsigned r[4], const void* p){
    uint32_t a = (uint32_t)__cvta_generic_to_shared(p);
    asm volatile("ldmatrix.sync.aligned.m8n8.x4.trans.shared.b16 {%0,%1,%2,%3}, [%4];\n"
        : "=r"(r[0]), "=r"(r[1]), "=r"(r[2]), "=r"(r[3]) : "r"(a));
}
// f32 accumulate (recall)
__device__ __forceinline__ void mma16816(float c[4], const unsigned a[4], unsigned b0, unsigned b1){
    asm volatile("mma.sync.aligned.m16n8k16.row.col.f32.f16.f16.f32 "
        "{%0,%1,%2,%3}, {%4,%5,%6,%7}, {%8,%9}, {%0,%1,%2,%3};\n"
        : "+f"(c[0]), "+f"(c[1]), "+f"(c[2]), "+f"(c[3])
        : "r"(a[0]), "r"(a[1]), "r"(a[2]), "r"(a[3]), "r"(b0), "r"(b1));
}
// f16 accumulate (logits)
__device__ __forceinline__ void mma16816h(unsigned c[2], const unsigned a[4], unsigned b0, unsigned b1){
    asm volatile("mma.sync.aligned.m16n8k16.row.col.f16.f16.f16.f16 "
        "{%0,%1}, {%2,%3,%4,%5}, {%6,%7}, {%0,%1};\n"
        : "+r"(c[0]), "+r"(c[1])
        : "r"(a[0]), "r"(a[1]), "r"(a[2]), "r"(a[3]), "r"(b0), "r"(b1));
}

// ------- fused convert + normalize + identity-embedding copy ---------------
__global__ void convert_norms_kernel(const float* __restrict__ face, const float* __restrict__ speech,
                                     const float* __restrict__ svm, const float* __restrict__ fkm,
                                     float* __restrict__ out_se, float* __restrict__ out_fe,
                                     int N, int S){
    int warp = threadIdx.x >> 5, lane = threadIdx.x & 31;
    int rid = blockIdx.x * 8 + warp;
    int total = 2*N + 2*S;
    if (rid >= total) return;
    const float* src; __half* hdst; __half* hraw = nullptr; float* fcopy = nullptr;
    if (rid < N)            { src = speech + (long)rid * 256; hdst = g_sp_h + (long)rid * 256;
                              fcopy = out_se + (long)rid * 256; }
    else if (rid < 2*N)     { int r = rid - N; src = face + (long)r * 256; hdst = g_fa_h + (long)r * 256;
                              fcopy = out_fe + (long)r * 256; }
    else if (rid < 2*N + S) { int r = rid - 2*N; src = svm + (long)r * 256;
                              hdst = g_svmn_h + (long)r * 256; hraw = g_svm_h + (long)r * 256; }
    else                    { int r = rid - 2*N - S; src = fkm + (long)r * 256; hdst = g_fkmn_h + (long)r * 256; }
    const float4* p = reinterpret_cast<const float4*>(src);
    float4 v0 = p[lane], v1 = p[lane + 32];
    float s = v0.x*v0.x + v0.y*v0.y + v0.z*v0.z + v0.w*v0.w
            + v1.x*v1.x + v1.y*v1.y + v1.z*v1.z + v1.w*v1.w;
    #pragma unroll
    for (int o = 16; o; o >>= 1) s += __shfl_xor_sync(0xffffffffu, s, o);
    float inv = rsqrtf(s);
    uint2* up = reinterpret_cast<uint2*>(hdst);
    up[lane]      = make_uint2(pkh(v0.x*inv, v0.y*inv), pkh(v0.z*inv, v0.w*inv));
    up[lane + 32] = make_uint2(pkh(v1.x*inv, v1.y*inv), pkh(v1.z*inv, v1.w*inv));
    if (hraw) {
        uint2* ur = reinterpret_cast<uint2*>(hraw);
        ur[lane]      = make_uint2(pkh(v0.x, v0.y), pkh(v0.z, v0.w));
        ur[lane + 32] = make_uint2(pkh(v1.x, v1.y), pkh(v1.z, v1.w));
    }
    if (fcopy) {
        float4* fp = reinterpret_cast<float4*>(fcopy);
        fp[lane] = v0;
        fp[lane + 32] = v1;
    }
}

// ---------------- logits GEMM: cos = Ahat @ Bhat^T --------------------------
// Normalized fp16 operands + FP16 ACCUMULATE. BM=128, BN=128, BK=64, 256 thr,
// 8 warps 4(m)x2(n). blockIdx.z = which. 3 CTAs/SM (fills epilogue gaps).
// Epilogue: P' = exp(cos+8) fp16 -> g_P; quad-reduced partial sumexp -> g_partial.
__global__ __launch_bounds__(256, 3) void logits_kernel(int N, int S)
{
    extern __shared__ __align__(16) char sm[];
    __half* As = (__half*)sm;              // [2][128][72]
    __half* Bs = (__half*)(sm + 36864);    // [2][128][72]
    const int which = blockIdx.z;
    const __half* A = which ? g_fa_h : g_sp_h;
    const __half* B = which ? g_fkmn_h : g_svmn_h;
    const int naoff = which ? N : 0;
    const int tid = threadIdx.x;
    const int warp = tid >> 5, lane = tid & 31;
    const int wm = warp >> 1, wn = warp & 1;
    const long bm = blockIdx.y, bn = blockIdx.x;
    const __half* Ab = A + bm * 128 * 256;
    const __half* Bb = B + bn * 128 * 256;
    uint32_t sa = (uint32_t)__cvta_generic_to_shared(As);
    uint32_t sb = (uint32_t)__cvta_generic_to_shared(Bs);
    const int lr = tid >> 3, lc = (tid & 7) * 8;   // chunk: 8 halves

    unsigned acc[2][8][2] = {};   // f16x2 accumulators

    // prologue: stage 0
    #pragma unroll
    for (int i = 0; i < 4; i++) {
        int r = lr + i * 32;
        cpa16(sa + (unsigned)(r * 72 + lc) * 2, Ab + r * 256 + lc);
        cpa16(sb + (unsigned)(r * 72 + lc) * 2, Bb + r * 256 + lc);
    }
    CP_COMMIT;

    for (int kb = 0; kb < 4; ++kb) {
        if (kb < 3) {
            int st = (kb + 1) & 1;
            #pragma unroll
            for (int i = 0; i < 4; i++) {
                int r = lr + i * 32;
                cpa16(sa + (unsigned)(st * 9216 + r * 72 + lc) * 2, Ab + r * 256 + (kb + 1) * 64 + lc);
                cpa16(sb + (unsigned)(st * 9216 + r * 72 + lc) * 2, Bb + r * 256 + (kb + 1) * 64 + lc);
            }
        }
        CP_COMMIT;
        CP_WAIT(1);
        __syncthreads();
        const __half* Ast = As + (kb & 1) * 9216;
        const __half* Bst = Bs + (kb & 1) * 9216;
        #pragma unroll
        for (int kk = 0; kk < 4; ++kk) {
            unsigned a[2][4], b[4][4];
            #pragma unroll
            for (int mt = 0; mt < 2; ++mt) {
                int r = wm * 32 + mt * 16 + (lane & 15);
                int c = kk * 16 + ((lane >> 4) << 3);
                ldsm4(a[mt], Ast + r * 72 + c);
            }
            #pragma unroll
            for (int np = 0; np < 4; ++np) {
                int g = lane >> 3;
                int r = wn * 64 + np * 16 + ((g >> 1) << 3) + (lane & 7);
                int c = kk * 16 + ((g & 1) << 3);
                ldsm4(b[np], Bst + r * 72 + c);
            }
            #pragma unroll
            for (int mt = 0; mt < 2; ++mt)
                #pragma unroll
                for (int nt = 0; nt < 8; ++nt)
                    mma16816h(acc[mt][nt], a[mt], b[nt >> 1][(nt & 1) * 2], b[nt >> 1][(nt & 1) * 2 + 1]);
        }
        __syncthreads();
    }

    #pragma unroll
    for (int mt = 0; mt < 2; ++mt) {
        int r = (int)(bm * 128) + wm * 32 + mt * 16 + (lane >> 2);
        float ps0 = 0.f, ps1 = 0.f;
        #pragma unroll
        for (int nt = 0; nt < 8; ++nt) {
            int c = (int)(bn * 128) + wn * 64 + nt * 8 + (lane & 3) * 2;
            float2 f0 = __half22float2(*reinterpret_cast<__half2*>(&acc[mt][nt][0]));
            float2 f1 = __half22float2(*reinterpret_cast<__half2*>(&acc[mt][nt][1]));
            float e00 = __expf(f0.x), e01 = __expf(f0.y);
            float e10 = __expf(f1.x), e11 = __expf(f1.y);
            ps0 += e00 + e01;
            ps1 += e10 + e11;
            *reinterpret_cast<unsigned*>(&g_P[(long)(naoff + r) * S + c]) = pkh(e00 * E8F, e01 * E8F);
            *reinterpret_cast<unsigned*>(&g_P[(long)(naoff + r + 8) * S + c]) = pkh(e10 * E8F, e11 * E8F);
        }
        // quad reduction (lanes differing in bits 0,1 share the same rows)
        ps0 += __shfl_xor_sync(0xffffffffu, ps0, 1);
        ps0 += __shfl_xor_sync(0xffffffffu, ps0, 2);
        ps1 += __shfl_xor_sync(0xffffffffu, ps1, 1);
        ps1 += __shfl_xor_sync(0xffffffffu, ps1, 2);
        if ((lane & 3) == 0) {
            int chunk = (int)bn * 2 + wn;
            g_partial[(long)(naoff + r) * 64 + chunk] = ps0;
            g_partial[(long)(naoff + r + 8) * 64 + chunk] = ps1;
        }
    }
}

// ---------------- recall GEMM (pure fp16 operands) + addr_log --------------
// P' and V tiles via cp.async (2 stages, ONE barrier/iter). 2 CTAs/SM.
// addr_log = ln(P') - 8 - ln(s), streamed out via __stcs (never re-read).
// recall = (exp(-8)/sumexp) * (P' @ V). BM=64, BN=256, BK=64, warps 2x4.
__global__ __launch_bounds__(256, 2) void recall_kernel(
    float* __restrict__ logits0, float* __restrict__ logits1,
    float* __restrict__ outR0, float* __restrict__ outR1, int N, int S)
{
    extern __shared__ __align__(16) char sm[];
    __half* Vs = (__half*)sm;                  // [2][64][264]
    __half* Ps = (__half*)(sm + 67584);        // [2][64][72]
    float*  Lsp = (float*)(sm + 86016);        // 64: PSHIFT + ln(sumexp)
    float*  Si  = (float*)(sm + 86272);        // 64: exp(-8)/sumexp
    const __half* V = g_svm_h;   // both recalls use raw speech_value_memory
    const int which = blockIdx.y;
    float* logits = which ? logits1 : logits0;
    float* outR   = which ? outR1   : outR0;
    const int lseoff = which ? N : 0;
    const int tid = threadIdx.x;
    const int warp = tid >> 5, lane = tid & 31;
    const int wm = warp >> 2, wn = warp & 3;
    const long bm = blockIdx.x;
    float* Lg = logits + bm * 64 * (long)S;
    const __half* Pg = g_P + (long)(lseoff + bm * 64) * S;
    uint32_t sv = (uint32_t)__cvta_generic_to_shared(Vs);
    uint32_t sp = (uint32_t)__cvta_generic_to_shared(Ps);

    if (tid < 64) {
        const float4* pp = reinterpret_cast<const float4*>(g_partial + (long)(lseoff + bm * 64 + tid) * 64);
        float s = 0.f;
        #pragma unroll
        for (int j = 0; j < 16; j++) { float4 v = pp[j]; s += v.x + v.y + v.z + v.w; }
        Lsp[tid] = PSHIFT + logf(s);
        Si[tid]  = PSCALE / s;
    }

    float acc[2][8][4] = {};

    // prologue: stage 0
    #pragma unroll
    for (int i = 0; i < 8; i++) {
        int idx = tid + i * 256, r = idx >> 5, c = idx & 31;
        cpa16(sv + (unsigned)(r * 264 + c * 8) * 2, V + (long)r * 256 + c * 8);
    }
    #pragma unroll
    for (int i = 0; i < 2; i++) {
        int idx = tid + i * 256, r = idx >> 3, c8 = (idx & 7) * 8;
        cpa16(sp + (unsigned)(r * 72 + c8) * 2, Pg + (long)r * S + c8);
    }
    CP_COMMIT;

    const int KB = S / 64;
    for (int kb = 0; kb < KB; ++kb) {
        CP_WAIT(0);
        __syncthreads();
        if (kb < KB - 1) {
            int st = (kb + 1) & 1;
            #pragma unroll
            for (int i = 0; i < 8; i++) {
                int idx = tid + i * 256, r = idx >> 5, c = idx & 31;
                cpa16(sv + (unsigned)(st * 16896 + r * 264 + c * 8) * 2,
                      V + (long)((kb + 1) * 64 + r) * 256 + c * 8);
            }
            #pragma unroll
            for (int i = 0; i < 2; i++) {
                int idx = tid + i * 256, r = idx >> 3, c8 = (idx & 7) * 8;
                cpa16(sp + (unsigned)(st * 4608 + r * 72 + c8) * 2,
                      Pg + (long)r * S + (kb + 1) * 64 + c8);
            }
            CP_COMMIT;
        }
        const int st = kb & 1;
        // addr_log from the P' tile: ln(P') - (8 + ln(s)); streamed stores
        #pragma unroll
        for (int i = 0; i < 2; i++) {
            int idx = tid + i * 256, r = idx >> 3, c8 = (idx & 7) * 8;
            const __half2* ph = reinterpret_cast<const __half2*>(Ps + st * 4608 + r * 72 + c8);
            float lsp = Lsp[r];
            float2 a0 = __half22float2(ph[0]);
            float2 a1 = __half22float2(ph[1]);
            float2 a2 = __half22float2(ph[2]);
            float2 a3 = __half22float2(ph[3]);
            float4 o0, o1;
            o0.x = __logf(a0.x) - lsp; o0.y = __logf(a0.y) - lsp;
            o0.z = __logf(a1.x) - lsp; o0.w = __logf(a1.y) - lsp;
            o1.x = __logf(a2.x) - lsp; o1.y = __logf(a2.y) - lsp;
            o1.z = __logf(a3.x) - lsp; o1.w = __logf(a3.y) - lsp;
            float* op = Lg + (long)r * S + kb * 64 + c8;
            __stcs(reinterpret_cast<float4*>(op), o0);
            __stcs(reinterpret_cast<float4*>(op + 4), o1);
        }
        const __half* Pst = Ps + st * 4608;
        const __half* Vst = Vs + st * 16896;
        #pragma unroll
        for (int kk = 0; kk < 4; ++kk) {
            unsigned a[2][4], b[4][4];
            #pragma unroll
            for (int mt = 0; mt < 2; ++mt) {
                int r = wm * 32 + mt * 16 + (lane & 15);
                int c = kk * 16 + ((lane >> 4) << 3);
                ldsm4(a[mt], Pst + r * 72 + c);
            }
            #pragma unroll
            for (int np = 0; np < 4; ++np) {   // V rows=k, cols=n -> trans
                int g = lane >> 3;
                int r = kk * 16 + ((g & 1) << 3) + (lane & 7);
                int c = wn * 64 + np * 16 + ((g >> 1) << 3);
                ldsm4t(b[np], Vst + r * 264 + c);
            }
            #pragma unroll
            for (int mt = 0; mt < 2; ++mt)
                #pragma unroll
                for (int nt = 0; nt < 8; ++nt)
                    mma16816(acc[mt][nt], a[mt], b[nt >> 1][(nt & 1) * 2], b[nt >> 1][(nt & 1) * 2 + 1]);
        }
    }

    #pragma unroll
    for (int mt = 0; mt < 2; ++mt) {
        int rl = wm * 32 + mt * 16 + (lane >> 2);
        int r = (int)(bm * 64) + rl;
        float s0 = Si[rl], s1 = Si[rl + 8];
        #pragma unroll
        for (int nt = 0; nt < 8; ++nt) {
            int c = wn * 64 + nt * 8 + (lane & 3) * 2;
            __stcs(reinterpret_cast<float2*>(outR + (long)r * 256 + c),
                   make_float2(acc[mt][nt][0] * s0, acc[mt][nt][1] * s0));
            __stcs(reinterpret_cast<float2*>(outR + (long)(r + 8) * 256 + c),
                   make_float2(acc[mt][nt][2] * s1, acc[mt][nt][3] * s1));
        }
    }
}

// ---------------------------------------------------------------------------
static const int LOG_SMEM = 73728;
static const int REC_SMEM = 86528;

extern "C" void kernel_launch(void* const* d_in, const int* in_sizes, int n_in,
                              void* d_out, int out_size) {
    const float* face   = (const float*)d_in[0];
    const float* speech = (const float*)d_in[1];
    const float* svm    = (const float*)d_in[2];
    const float* fkm    = (const float*)d_in[3];
    const int C = 256;
    const int N = in_sizes[0] / C;   // 8192
    const int S = in_sizes[2] / C;   // 4096
    float* out = (float*)d_out;
    const long NC = (long)N * C;
    const long NS = (long)N * S;

    float* o_semb = out;               // speech_emb
    float* o_srec = out + NC;          // speech_emb_recall
    float* o_femb = out + 2 * NC;      // face_emb
    float* o_frec = out + 3 * NC;      // face_emb_recall
    float* o_slog = out + 4 * NC;      // speech_address_log
    float* o_flog = out + 4 * NC + NS; // face_address_log

    cudaFuncSetAttribute(logits_kernel, cudaFuncAttributeMaxDynamicSharedMemorySize, LOG_SMEM);
    cudaFuncSetAttribute(recall_kernel, cudaFuncAttributeMaxDynamicSharedMemorySize, REC_SMEM);

    int rows = 2 * N + 2 * S;
    convert_norms_kernel<<<(rows + 7) / 8, 256>>>(face, speech, svm, fkm, o_semb, o_femb, N, S);

    dim3 g2(S / 128, N / 128, 2);
    logits_kernel<<<g2, 256, LOG_SMEM>>>(N, S);

    dim3 g3(N / 64, 2);
    recall_kernel<<<g3, 256, REC_SMEM>>>(o_slog, o_flog, o_srec, o_frec, N, S);
}